// round 11
// baseline (speedup 1.0000x reference)
#include <cuda_runtime.h>
#include <cuda_fp16.h>
#include <math.h>
#include <string.h>

#define Bz   1024
#define Nn   16
#define OBS  128
#define ACTD 32
#define RH   256
#define SH   256
#define KK   8
#define Ee   240
#define BN_  (Bz*Nn)   // 16384

// ---------------- scratch (__device__ globals; no allocation) ----------------
__device__ float g_gx  [BN_*768];
__device__ float g_gh  [BN_*768];
__device__ float g_pb  [1024];
__device__ float g_pb2 [16*512];
__device__ float g_wihc[768];

__device__ __align__(256) __half g_obs16 [BN_*128];
__device__ __align__(256) __half g_h016  [BN_*256];
__device__ __align__(256) __half g_hid16 [BN_*256];
__device__ __align__(256) __half g_node16[BN_*1024];
__device__ __align__(256) __half g_S16   [BN_*256];
__device__ __align__(256) __half g_msgs16[BN_*1024];
__device__ __align__(256) __half g_ai16  [BN_*256];
__device__ __align__(256) __half g_h116  [BN_*512];
__device__ __align__(256) __half g_wih16 [768*128];
__device__ __align__(256) __half g_whh16 [768*256];
__device__ __align__(256) __half g_pw16  [1024*256];
__device__ __align__(256) __half g_dw216 [129*256];
__device__ __align__(256) __half g_msgw16[1024*128];
__device__ __align__(256) __half g_pw216 [16*512*256];
__device__ __align__(256) __half g_aw216 [16*32*256];

// ---------------- helpers ----------------
__device__ __forceinline__ unsigned smem_u32(const void* p) {
    unsigned a;
    asm("{ .reg .u64 t; cvta.to.shared.u64 t, %1; cvt.u32.u64 %0, t; }" : "=r"(a) : "l"(p));
    return a;
}

__device__ __forceinline__ void mma_fp16(float* c, const unsigned* a, const unsigned* b) {
    asm volatile(
        "mma.sync.aligned.m16n8k16.row.col.f32.f16.f16.f32 "
        "{%0,%1,%2,%3}, {%4,%5,%6,%7}, {%8,%9}, {%0,%1,%2,%3};"
        : "+f"(c[0]), "+f"(c[1]), "+f"(c[2]), "+f"(c[3])
        : "r"(a[0]), "r"(a[1]), "r"(a[2]), "r"(a[3]), "r"(b[0]), "r"(b[1]));
}

__device__ __forceinline__ void ldsm4(unsigned* r, unsigned addr) {
    asm volatile("ldmatrix.sync.aligned.m8n8.x4.shared.b16 {%0,%1,%2,%3}, [%4];"
                 : "=r"(r[0]), "=r"(r[1]), "=r"(r[2]), "=r"(r[3]) : "r"(addr));
}

// ---------------- fp16 tensor-core GEMM (fp16 LDG.128 staging, reg-prefetch double buffer)
// C/C16 = (A@B^T + bias*biasMul + rowv*colv)*scale [,relu]
// A:[M,K] lda halves; B:[N,K] ldb halves; z-batched via strides (element units).
// Block 128x128, BK=32. Requires M%128==0, K%32==0, lda/ldb%8==0, 16B-aligned bases.
#define ATB 10240   // 128 rows * 80 bytes

__global__ void __launch_bounds__(256, 2) gemm_h4(
    const __half* __restrict__ A, int lda, long long sA,
    const __half* __restrict__ B, int ldb, long long sB,
    const float* __restrict__ bias, long long sBias, float biasMul,
    const float* __restrict__ rowv, const float* __restrict__ colv, int cvs,
    float* __restrict__ C, __half* __restrict__ C16, int ldc, long long sC,
    int M, int N, int K, float scale, int relu)
{
    __shared__ __align__(16) char sm[2][2 * ATB];   // [buf][A|B]

    int t = threadIdx.x;
    int wid = t >> 5, lane = t & 31;
    int bz = blockIdx.z;
    A += (long long)bz * sA;
    B += (long long)bz * sB;
    const float* bp = bias ? bias + (long long)bz * sBias : (const float*)0;
    int row0 = blockIdx.y * 128;
    int col0 = blockIdx.x * 128;

    int wm0 = (wid & 1) * 64;        // 2 warps in M
    int wn0 = (wid >> 1) * 32;       // 4 warps in N
    int mrow = lane >> 2, kr = lane & 3;

    float acc[16][4];
    #pragma unroll
    for (int i = 0; i < 16; i++)
        #pragma unroll
        for (int j = 0; j < 4; j++) acc[i][j] = 0.f;

    // staging slice: p = q*256 + t; row = p>>2 (0..127), g = p&3 (16B segment)
    int srow = t >> 2, sg = t & 3;

    uint4 ra[2], rb[2];
    const __half* arow0 = A + (long long)(row0 + srow) * lda + sg * 8;
    const __half* arow1 = A + (long long)(row0 + srow + 64) * lda + sg * 8;
    int gc0 = col0 + srow, gc1 = col0 + srow + 64;
    const __half* brow0 = B + (long long)((gc0 < N) ? gc0 : 0) * ldb + sg * 8;
    const __half* brow1 = B + (long long)((gc1 < N) ? gc1 : 0) * ldb + sg * 8;

    // ---- prologue: chunk 0 ----
    ra[0] = *(const uint4*)(arow0);
    ra[1] = *(const uint4*)(arow1);
    rb[0] = *(const uint4*)(brow0);
    rb[1] = *(const uint4*)(brow1);
    {
        char* d = sm[0];
        *(uint4*)(d + srow * 80 + sg * 16)              = ra[0];
        *(uint4*)(d + (srow + 64) * 80 + sg * 16)       = ra[1];
        *(uint4*)(d + ATB + srow * 80 + sg * 16)        = rb[0];
        *(uint4*)(d + ATB + (srow + 64) * 80 + sg * 16) = rb[1];
    }
    __syncthreads();

    unsigned sbase = smem_u32(sm);
    int buf = 0;
    int tl = lane >> 3, rl = lane & 7;
    for (int k0 = 0; k0 < K; k0 += 32) {
        bool next = (k0 + 32) < K;
        if (next) {
            int kn = k0 + 32;
            ra[0] = *(const uint4*)(arow0 + kn);
            ra[1] = *(const uint4*)(arow1 + kn);
            rb[0] = *(const uint4*)(brow0 + kn);
            rb[1] = *(const uint4*)(brow1 + kn);
        }

        unsigned abase = sbase + buf * (2 * ATB);
        unsigned bbase = abase + ATB;
        #pragma unroll
        for (int s = 0; s < 2; s++) {
            int ks = s * 16;
            unsigned afr[4][4], bfr[4][2];
            #pragma unroll
            for (int mt = 0; mt < 4; mt++) {
                int m0 = wm0 + mt * 16;
                int row = m0 + rl + ((tl & 1) << 3);
                int col = ks + ((tl >> 1) << 3);
                ldsm4(afr[mt], abase + row * 80 + col * 2);
            }
            #pragma unroll
            for (int nb = 0; nb < 2; nb++) {
                int n0 = wn0 + nb * 16;
                int row = n0 + rl + ((tl >> 1) << 3);
                int col = ks + ((tl & 1) << 3);
                unsigned r4[4];
                ldsm4(r4, bbase + row * 80 + col * 2);
                bfr[nb * 2 + 0][0] = r4[0]; bfr[nb * 2 + 0][1] = r4[1];
                bfr[nb * 2 + 1][0] = r4[2]; bfr[nb * 2 + 1][1] = r4[3];
            }
            #pragma unroll
            for (int mt = 0; mt < 4; mt++)
                #pragma unroll
                for (int nt = 0; nt < 4; nt++)
                    mma_fp16(acc[mt * 4 + nt], afr[mt], bfr[nt]);
        }

        if (next) {
            char* d = sm[buf ^ 1];
            *(uint4*)(d + srow * 80 + sg * 16)              = ra[0];
            *(uint4*)(d + (srow + 64) * 80 + sg * 16)       = ra[1];
            *(uint4*)(d + ATB + srow * 80 + sg * 16)        = rb[0];
            *(uint4*)(d + ATB + (srow + 64) * 80 + sg * 16) = rb[1];
        }
        __syncthreads();
        buf ^= 1;
    }

    // ---- epilogue ----
    float* Cp = C ? C + (long long)bz * sC : (float*)0;
    __half* Cq = C16 ? C16 + (long long)bz * sC : (__half*)0;
    #pragma unroll
    for (int mt = 0; mt < 4; mt++) {
        int r0 = row0 + wm0 + mt * 16 + mrow;
        #pragma unroll
        for (int nt = 0; nt < 4; nt++) {
            int cbase = col0 + wn0 + nt * 8 + 2 * kr;
            const float* cc = acc[mt * 4 + nt];
            #pragma unroll
            for (int h = 0; h < 2; h++) {
                int gr = r0 + h * 8;
                #pragma unroll
                for (int w2 = 0; w2 < 2; w2++) {
                    int gc = cbase + w2;
                    if (gc < N) {
                        float v = cc[h * 2 + w2];
                        if (bp) v += bp[gc] * biasMul;
                        if (rowv) v += rowv[gr] * colv[(long long)gc * cvs];
                        v *= scale;
                        if (relu) v = fmaxf(v, 0.f);
                        if (Cp) Cp[(long long)gr * ldc + gc] = v;
                        if (Cq) Cq[(long long)gr * ldc + gc] = __float2half_rn(v);
                    }
                }
            }
        }
    }
}

// ---------------- fused weight prelude (all converts/packs in one launch) --------
#define PRE_W_TOT (196608 + 33024 + 131072 + 131072 + 98304 + 768 + 262144 + 1024 + 2097152 + 8192)

__global__ void prelude_w_k(
    const float* __restrict__ w_hh, const float* __restrict__ dec_w2,
    const float* __restrict__ msg_w, const float* __restrict__ aw2,
    const float* __restrict__ w_ih,
    const float* __restrict__ ew1, const float* __restrict__ eb1,
    const float* __restrict__ dw1, const float* __restrict__ db1,
    const float* __restrict__ aw1, const float* __restrict__ ab1,
    const float* __restrict__ cw1, const float* __restrict__ cb1,
    __half* __restrict__ whh16, __half* __restrict__ dw216,
    __half* __restrict__ msgw16, __half* __restrict__ aw216,
    __half* __restrict__ wih16, float* __restrict__ wihc,
    __half* __restrict__ pw16, float* __restrict__ pb,
    __half* __restrict__ pw216, float* __restrict__ pb2)
{
    long long i = (long long)blockIdx.x * 256 + threadIdx.x;
    if (i >= PRE_W_TOT) return;
    if (i < 196608) { whh16[i] = __float2half_rn(w_hh[i]); return; }
    i -= 196608;
    if (i < 33024) { dw216[i] = __float2half_rn(dec_w2[i]); return; }
    i -= 33024;
    if (i < 131072) { msgw16[i] = __float2half_rn(msg_w[i]); return; }
    i -= 131072;
    if (i < 131072) { aw216[i] = __float2half_rn(aw2[i]); return; }
    i -= 131072;
    if (i < 98304) {
        int r = (int)(i >> 7), c = (int)(i & 127);
        wih16[i] = __float2half_rn(w_ih[r * 129 + c]);
        return;
    }
    i -= 98304;
    if (i < 768) { wihc[i] = w_ih[i * 129 + 128]; return; }
    i -= 768;
    if (i < 262144) {
        int r = (int)(i >> 8), c = (int)(i & 255);
        float v;
        if (r < 256)      v = ew1[r * 512 + c];
        else if (r < 512) v = ew1[(r - 256) * 512 + 256 + c];
        else if (r < 768) v = dw1[(r - 512) * 512 + c];
        else              v = dw1[(r - 768) * 512 + 256 + c];
        pw16[i] = __float2half_rn(v);
        return;
    }
    i -= 262144;
    if (i < 1024) {
        int r = (int)i;
        float v = 0.f;
        if (r >= 256 && r < 512) v = eb1[r - 256];
        else if (r >= 768)       v = db1[r - 768];
        pb[r] = v;
        return;
    }
    i -= 1024;
    if (i < 2097152) {
        int n = (int)(i >> 17);
        int r = (int)((i >> 8) & 511);
        int c = (int)(i & 255);
        float v = (r < 256) ? aw1[n * 65536 + r * 256 + c]
                            : cw1[n * 65536 + (r - 256) * 256 + c];
        pw216[i] = __float2half_rn(v);
        return;
    }
    i -= 2097152;
    {
        int n = (int)(i >> 9), r = (int)(i & 511);
        pb2[i] = (r < 256) ? ab1[n * 256 + r] : cb1[n * 256 + r - 256];
    }
}

// ---------------- activation prelude: obs16 + h016 ----------------
__global__ void prelude_a_k(const float* __restrict__ obs, const float* __restrict__ h0,
                            __half* __restrict__ obs16, __half* __restrict__ h016)
{
    long long i4 = (long long)blockIdx.x * 256 + threadIdx.x;
    if (i4 >= (BN_ * 128 + BN_ * 256) / 4) return;
    const float* s;
    __half* d;
    long long off;
    if (i4 < BN_ * 128 / 4) { s = obs; d = obs16; off = i4 * 4; }
    else { s = h0; d = h016; off = (i4 - BN_ * 128 / 4) * 4; }
    float4 v = *(const float4*)(s + off);
    *(__half2*)(d + off)     = __floats2half2_rn(v.x, v.y);
    *(__half2*)(d + off + 2) = __floats2half2_rn(v.z, v.w);
}

// ---------------- GRU gates (float4), writes fp32 hidden + fp16 mirror ----------------
__global__ void gru_gate4_k(const float* __restrict__ gx, const float* __restrict__ gh,
                            const float* __restrict__ h0, float* __restrict__ h,
                            __half* __restrict__ h16)
{
    int idx = blockIdx.x * blockDim.x + threadIdx.x;  // over BN_*64
    if (idx >= BN_ * 64) return;
    int m = idx >> 6;
    int c4 = (idx & 63) * 4;
    long long bx = (long long)m * 768 + c4;
    float4 xr = *(const float4*)(gx + bx);
    float4 xz = *(const float4*)(gx + bx + 256);
    float4 xn = *(const float4*)(gx + bx + 512);
    float4 hr = *(const float4*)(gh + bx);
    float4 hz = *(const float4*)(gh + bx + 256);
    float4 hn = *(const float4*)(gh + bx + 512);
    float4 h0v = *(const float4*)(h0 + (long long)m * 256 + c4);
    float4 o;
    {
        float r = 1.f / (1.f + expf(-(xr.x + hr.x)));
        float z = 1.f / (1.f + expf(-(xz.x + hz.x)));
        float nc = tanhf(xn.x + r * hn.x);
        o.x = (1.f - z) * nc + z * h0v.x;
    }
    {
        float r = 1.f / (1.f + expf(-(xr.y + hr.y)));
        float z = 1.f / (1.f + expf(-(xz.y + hz.y)));
        float nc = tanhf(xn.y + r * hn.y);
        o.y = (1.f - z) * nc + z * h0v.y;
    }
    {
        float r = 1.f / (1.f + expf(-(xr.z + hr.z)));
        float z = 1.f / (1.f + expf(-(xz.z + hz.z)));
        float nc = tanhf(xn.z + r * hn.z);
        o.z = (1.f - z) * nc + z * h0v.z;
    }
    {
        float r = 1.f / (1.f + expf(-(xr.w + hr.w)));
        float z = 1.f / (1.f + expf(-(xz.w + hz.w)));
        float nc = tanhf(xn.w + r * hn.w);
        o.w = (1.f - z) * nc + z * h0v.w;
    }
    *(float4*)(h + (long long)m * 256 + c4) = o;
    *(__half2*)(h16 + (long long)m * 256 + c4)     = __floats2half2_rn(o.x, o.y);
    *(__half2*)(h16 + (long long)m * 256 + c4 + 2) = __floats2half2_rn(o.z, o.w);
}

// ---------------- fused per-batch edge kernel (fp16 node projections) ----------------
__global__ __launch_bounds__(256) void edge_k(
    const __half* __restrict__ node,         // [B*N, 1024]: eHs|eHr|dHs|dHr
    const float* __restrict__ w2, const float* __restrict__ b2,
    float* __restrict__ rel, __half* __restrict__ Sout)
{
    __shared__ float sW2[KK * SH];
    __shared__ float sS[Nn][SH];
    int b = blockIdx.x;
    int tid = threadIdx.x;
    for (int i = tid; i < KK * SH; i += 256) sW2[i] = w2[i];
    for (int i = tid; i < Nn * SH; i += 256) (&sS[0][0])[i] = 0.f;
    __syncthreads();

    int w = tid >> 5, lane = tid & 31;
    long long base = (long long)b * Nn * 1024;
    for (int ii = 0; ii < 2; ii++) {
        int i = w * 2 + ii;
        float eR[8], dR[8];
        #pragma unroll
        for (int q = 0; q < 8; q++) {
            int c = lane + 32 * q;
            eR[q] = __half2float(node[base + i * 1024 + 256 + c]);
            dR[q] = __half2float(node[base + i * 1024 + 768 + c]);
        }
        for (int j = 0; j < Nn; j++) {
            if (j == i) continue;
            float part[KK];
            #pragma unroll
            for (int k = 0; k < KK; k++) part[k] = 0.f;
            #pragma unroll
            for (int q = 0; q < 8; q++) {
                int c = lane + 32 * q;
                float pe = __half2float(node[base + j * 1024 + c]) + eR[q];
                pe = fmaxf(pe, 0.f);
                #pragma unroll
                for (int k = 0; k < KK; k++) part[k] += pe * sW2[k * SH + c];
                float pd = __half2float(node[base + j * 1024 + 512 + c]) + dR[q];
                pd = fmaxf(pd, 0.f);
                sS[i][c] += pd;
            }
            #pragma unroll
            for (int k = 0; k < KK; k++) {
                #pragma unroll
                for (int off = 16; off; off >>= 1)
                    part[k] += __shfl_xor_sync(0xffffffffu, part[k], off);
                part[k] += b2[k];
            }
            if (lane == 0) {
                float mx = part[0];
                #pragma unroll
                for (int k = 1; k < KK; k++) mx = fmaxf(mx, part[k]);
                float e_[KK], s = 0.f;
                #pragma unroll
                for (int k = 0; k < KK; k++) { e_[k] = expf(part[k] - mx); s += e_[k]; }
                float inv = 1.f / s;
                int jj = (j < i) ? j : j - 1;
                long long eo = ((long long)b * Ee + i * 15 + jj) * KK;
                #pragma unroll
                for (int k = 0; k < KK; k++) rel[eo + k] = e_[k] * inv;
            }
        }
    }
    __syncthreads();
    long long sb = (long long)b * Nn * SH;
    for (int i = tid; i < Nn * SH; i += 256)
        Sout[sb + i] = __float2half_rn((&sS[0][0])[i]);
}

// ---------------- message aggregation + build ai16 = [obs, message] ----------------
__global__ __launch_bounds__(256) void message_k(
    const float* __restrict__ rel, const __half* __restrict__ msgs,
    const __half* __restrict__ obs16, __half* __restrict__ ai16)
{
    __shared__ float sRel[Ee * KK];  // 1920
    int b = blockIdx.x;
    int tid = threadIdx.x;
    for (int i = tid; i < Ee * KK; i += 256) sRel[i] = rel[(long long)b * Ee * KK + i];
    __syncthreads();

    int d = tid & 127;
    int g = tid >> 7;
    float acc[8];
    #pragma unroll
    for (int ii = 0; ii < 8; ii++) acc[ii] = 0.f;
    long long mb = (long long)b * Nn * KK * OBS;
    for (int j = 0; j < Nn; j++) {
        float mj[KK];
        #pragma unroll
        for (int k = 0; k < KK; k++) mj[k] = __half2float(msgs[mb + (j * KK + k) * OBS + d]);
        #pragma unroll
        for (int ii = 0; ii < 8; ii++) {
            int i = g * 8 + ii;
            if (i == j) continue;
            int jj = (j < i) ? j : j - 1;
            const float* r = &sRel[(i * 15 + jj) * KK];
            float a = acc[ii];
            #pragma unroll
            for (int k = 0; k < KK; k++) a += r[k] * mj[k];
            acc[ii] = a;
        }
    }
    long long ab = (long long)b * Nn * 2 * OBS;
    #pragma unroll
    for (int ii = 0; ii < 8; ii++) {
        int i = g * 8 + ii;
        ai16[ab + i * 2 * OBS + OBS + d] = __float2half_rn(acc[ii]);
    }
    for (int idx = tid; idx < Nn * OBS; idx += 256) {
        int i = idx >> 7, dd = idx & 127;
        ai16[ab + i * 2 * OBS + dd] = obs16[(long long)b * Nn * OBS + idx];
    }
}

// ---------------- critic layer 2 (N=1): one warp per (b,n) dot ----------------
__global__ void critic2_k(const __half* __restrict__ h1, const float* __restrict__ w2,
                          const float* __restrict__ b2v, float* __restrict__ out)
{
    int w = (blockIdx.x * blockDim.x + threadIdx.x) >> 5;
    int lane = threadIdx.x & 31;
    if (w >= BN_) return;
    int n = w & 15;
    float s = 0.f;
    #pragma unroll
    for (int q = 0; q < 8; q++) {
        int c = lane + 32 * q;
        s += __half2float(h1[(long long)w * 512 + 256 + c]) * w2[n * 256 + c];
    }
    #pragma unroll
    for (int off = 16; off; off >>= 1) s += __shfl_xor_sync(0xffffffffu, s, off);
    if (lane == 0) out[w] = s + b2v[n];
}

// ---------------- launch ----------------
extern "C" void kernel_launch(void* const* d_in, const int* in_sizes, int n_in,
                              void* d_out, int out_size)
{
    const float* obs    = (const float*)d_in[0];
    const float* rew    = (const float*)d_in[1];
    const float* h0     = (const float*)d_in[2];
    const float* w_ih   = (const float*)d_in[3];
    const float* w_hh   = (const float*)d_in[4];
    const float* b_ih   = (const float*)d_in[5];
    const float* b_hh   = (const float*)d_in[6];
    const float* enc_w1 = (const float*)d_in[7];
    const float* enc_b1 = (const float*)d_in[8];
    const float* enc_w2 = (const float*)d_in[9];
    const float* enc_b2 = (const float*)d_in[10];
    const float* dec_w1 = (const float*)d_in[11];
    const float* dec_b1 = (const float*)d_in[12];
    const float* dec_w2 = (const float*)d_in[13];
    const float* dec_b2 = (const float*)d_in[14];
    const float* msg_w  = (const float*)d_in[15];
    const float* msg_b  = (const float*)d_in[16];
    const float* aw1    = (const float*)d_in[17];
    const float* ab1    = (const float*)d_in[18];
    const float* aw2    = (const float*)d_in[19];
    const float* ab2    = (const float*)d_in[20];
    const float* cw1    = (const float*)d_in[21];
    const float* cb1    = (const float*)d_in[22];
    const float* cw2    = (const float*)d_in[23];
    const float* cb2    = (const float*)d_in[24];
    float* out = (float*)d_out;

    float *pgx, *pgh, *pb, *pb2, *pwihc;
    __half *obs16, *h016, *hid16, *node16, *S16, *msgs16, *ai16, *h116;
    __half *wih16, *whh16, *pw16, *dw216, *msgw16, *pw216, *aw216;
    cudaGetSymbolAddress((void**)&pgx,    g_gx);
    cudaGetSymbolAddress((void**)&pgh,    g_gh);
    cudaGetSymbolAddress((void**)&pb,     g_pb);
    cudaGetSymbolAddress((void**)&pb2,    g_pb2);
    cudaGetSymbolAddress((void**)&pwihc,  g_wihc);
    cudaGetSymbolAddress((void**)&obs16,  g_obs16);
    cudaGetSymbolAddress((void**)&h016,   g_h016);
    cudaGetSymbolAddress((void**)&hid16,  g_hid16);
    cudaGetSymbolAddress((void**)&node16, g_node16);
    cudaGetSymbolAddress((void**)&S16,    g_S16);
    cudaGetSymbolAddress((void**)&msgs16, g_msgs16);
    cudaGetSymbolAddress((void**)&ai16,   g_ai16);
    cudaGetSymbolAddress((void**)&h116,   g_h116);
    cudaGetSymbolAddress((void**)&wih16,  g_wih16);
    cudaGetSymbolAddress((void**)&whh16,  g_whh16);
    cudaGetSymbolAddress((void**)&pw16,   g_pw16);
    cudaGetSymbolAddress((void**)&dw216,  g_dw216);
    cudaGetSymbolAddress((void**)&msgw16, g_msgw16);
    cudaGetSymbolAddress((void**)&pw216,  g_pw216);
    cudaGetSymbolAddress((void**)&aw216,  g_aw216);

    float* actor  = out;                 // [B,N,32]    524288
    float* critic = out + 524288;        // [B,N,1]     16384
    float* scm    = out + 540672;        // [B,N,129]   2113536
    float* rel    = out + 2654208;       // [B,E,8]     1966080
    float* hid    = out + 4620288;       // [1,B*N,256] 4194304

    const float* NF = (const float*)0;
    float* NC = (float*)0;
    __half* NH = (__half*)0;

    // 1-2: fused preludes
    prelude_w_k<<<(PRE_W_TOT + 255) / 256, 256>>>(
        w_hh, dec_w2, msg_w, aw2, w_ih,
        enc_w1, enc_b1, dec_w1, dec_b1, aw1, ab1, cw1, cb1,
        whh16, dw216, msgw16, aw216, wih16, pwihc, pw16, pb, pw216, pb2);
    prelude_a_k<<<((BN_ * 384 / 4) + 255) / 256, 256>>>(obs, h0, obs16, h016);

    // GRU: gx = obs @ Wih[:, :128]^T + rew*Wih[:,128] + b_ih ; gh = h0 @ Whh^T + b_hh
    gemm_h4<<<dim3(6, 128, 1), 256>>>(
        obs16, 128, 0, wih16, 128, 0, b_ih, 0, 1.f, rew, pwihc, 1,
        pgx, NH, 768, 0, BN_, 768, 128, 1.f, 0);
    gemm_h4<<<dim3(6, 128, 1), 256>>>(
        h016, 256, 0, whh16, 256, 0, b_hh, 0, 1.f, NF, NF, 0,
        pgh, NH, 768, 0, BN_, 768, 256, 1.f, 0);
    gru_gate4_k<<<(BN_ * 64 + 255) / 256, 256>>>(pgx, pgh, h0, hid, hid16);

    // node projections [16384,1024] = hid @ pw^T + pb (fp16 out only)
    gemm_h4<<<dim3(8, 128, 1), 256>>>(
        hid16, 256, 0, pw16, 256, 0, pb, 0, 1.f, NF, NF, 0,
        NC, node16, 1024, 0, BN_, 1024, 256, 1.f, 0);

    edge_k<<<Bz, 256>>>(node16, enc_w2, enc_b2, rel, S16);

    // scm_pred = (S @ dec_w2^T + 15*b2) / 15.000001
    gemm_h4<<<dim3(2, 128, 1), 256>>>(
        S16, 256, 0, dw216, 256, 0, dec_b2, 0, 15.0f, NF, NF, 0,
        scm, NH, 129, 0, BN_, 129, 256, 1.f / 15.000001f, 0);

    // msgs: [16384,1024] = obs @ msg_w^T + msg_b (fp16 out only)
    gemm_h4<<<dim3(8, 128, 1), 256>>>(
        obs16, 128, 0, msgw16, 128, 0, msg_b, 0, 1.f, NF, NF, 0,
        NC, msgs16, 1024, 0, BN_, 1024, 128, 1.f, 0);

    message_k<<<Bz, 256>>>(rel, msgs16, obs16, ai16);

    // fused actor+critic layer 1, batched over agent: [1024,512] per agent (fp16 out)
    gemm_h4<<<dim3(4, 8, 16), 256>>>(
        ai16, 4096, 256, pw216, 256, 512 * 256, pb2, 512, 1.f, NF, NF, 0,
        NC, h116, 8192, 512, Bz, 512, 256, 1.f, 1);

    // actor layer 2 (N=32), batched over agent
    gemm_h4<<<dim3(1, 8, 16), 256>>>(
        h116, 8192, 512, aw216, 256, 32 * 256, ab2, 32, 1.f, NF, NF, 0,
        actor, NH, 512, 32, Bz, 32, 256, 1.f, 0);

    critic2_k<<<BN_ / 8, 256>>>(h116, cw2, cb2, critic);
}

// round 13
// speedup vs baseline: 1.3107x; 1.3107x over previous
#include <cuda_runtime.h>
#include <cuda_fp16.h>
#include <math.h>
#include <string.h>

#define Bz   1024
#define Nn   16
#define OBS  128
#define ACTD 32
#define RH   256
#define SH   256
#define KK   8
#define Ee   240
#define BN_  (Bz*Nn)   // 16384

// ---------------- scratch (__device__ globals; no allocation) ----------------
__device__ float g_gx  [BN_*768];
__device__ float g_gh  [BN_*768];
__device__ float g_pb  [1024];
__device__ float g_pb2 [16*512];
__device__ float g_wihc[768];

__device__ __align__(256) __half g_obs16 [BN_*128];
__device__ __align__(256) __half g_h016  [BN_*256];
__device__ __align__(256) __half g_hid16 [BN_*256];
__device__ __align__(256) __half g_node16[BN_*1024];
__device__ __align__(256) __half g_S16   [BN_*256];
__device__ __align__(256) __half g_msgs16[BN_*1024];
__device__ __align__(256) __half g_ai16  [BN_*256];
__device__ __align__(256) __half g_h116  [BN_*512];
__device__ __align__(256) __half g_wih16 [768*128];
__device__ __align__(256) __half g_whh16 [768*256];
__device__ __align__(256) __half g_pw16  [1024*256];
__device__ __align__(256) __half g_dw216 [129*256];
__device__ __align__(256) __half g_msgw16[1024*128];
__device__ __align__(256) __half g_pw216 [16*512*256];
__device__ __align__(256) __half g_aw216 [16*32*256];

// ---------------- helpers ----------------
__device__ __forceinline__ unsigned smem_u32(const void* p) {
    unsigned a;
    asm("{ .reg .u64 t; cvta.to.shared.u64 t, %1; cvt.u32.u64 %0, t; }" : "=r"(a) : "l"(p));
    return a;
}

__device__ __forceinline__ void mma_fp16(float* c, const unsigned* a, const unsigned* b) {
    asm volatile(
        "mma.sync.aligned.m16n8k16.row.col.f32.f16.f16.f32 "
        "{%0,%1,%2,%3}, {%4,%5,%6,%7}, {%8,%9}, {%0,%1,%2,%3};"
        : "+f"(c[0]), "+f"(c[1]), "+f"(c[2]), "+f"(c[3])
        : "r"(a[0]), "r"(a[1]), "r"(a[2]), "r"(a[3]), "r"(b[0]), "r"(b[1]));
}

__device__ __forceinline__ void ldsm4(unsigned* r, unsigned addr) {
    asm volatile("ldmatrix.sync.aligned.m8n8.x4.shared.b16 {%0,%1,%2,%3}, [%4];"
                 : "=r"(r[0]), "=r"(r[1]), "=r"(r[2]), "=r"(r[3]) : "r"(addr));
}

// ---------------- GEMM body: 128x128 tile, BK=32, fp16 LDG staging, reg-prefetch DB
// out = (A@B^T + bias*biasMul + rowv*colv)*scale [,relu]; exactly one of Cp/Cq non-null.
#define ATB 10240   // 128 rows * 80 bytes

__device__ __forceinline__ void gemm_body(
    const __half* __restrict__ A, int lda,
    const __half* __restrict__ B, int ldb,
    const float* __restrict__ bp, float biasMul,
    const float* __restrict__ rowv, const float* __restrict__ colv, int cvs,
    float* __restrict__ Cp, __half* __restrict__ Cq, int ldc,
    int row0, int col0, int N, int K, float scale, int relu)
{
    __shared__ __align__(16) char sm[2][2 * ATB];   // [buf][A|B]

    int t = threadIdx.x;
    int wid = t >> 5, lane = t & 31;
    int wm0 = (wid & 1) * 64;        // 2 warps in M
    int wn0 = (wid >> 1) * 32;       // 4 warps in N
    int mrow = lane >> 2, kr = lane & 3;

    float acc[16][4];
    #pragma unroll
    for (int i = 0; i < 16; i++)
        #pragma unroll
        for (int j = 0; j < 4; j++) acc[i][j] = 0.f;

    int srow = t >> 2, sg = t & 3;
    uint4 ra[2], rb[2];
    const __half* arow0 = A + (long long)(row0 + srow) * lda + sg * 8;
    const __half* arow1 = A + (long long)(row0 + srow + 64) * lda + sg * 8;
    int gc0 = col0 + srow, gc1 = col0 + srow + 64;
    const __half* brow0 = B + (long long)((gc0 < N) ? gc0 : 0) * ldb + sg * 8;
    const __half* brow1 = B + (long long)((gc1 < N) ? gc1 : 0) * ldb + sg * 8;

    ra[0] = *(const uint4*)(arow0);
    ra[1] = *(const uint4*)(arow1);
    rb[0] = *(const uint4*)(brow0);
    rb[1] = *(const uint4*)(brow1);
    {
        char* d = sm[0];
        *(uint4*)(d + srow * 80 + sg * 16)              = ra[0];
        *(uint4*)(d + (srow + 64) * 80 + sg * 16)       = ra[1];
        *(uint4*)(d + ATB + srow * 80 + sg * 16)        = rb[0];
        *(uint4*)(d + ATB + (srow + 64) * 80 + sg * 16) = rb[1];
    }
    __syncthreads();

    unsigned sbase = smem_u32(sm);
    int buf = 0;
    int tl = lane >> 3, rl = lane & 7;
    for (int k0 = 0; k0 < K; k0 += 32) {
        bool next = (k0 + 32) < K;
        if (next) {
            int kn = k0 + 32;
            ra[0] = *(const uint4*)(arow0 + kn);
            ra[1] = *(const uint4*)(arow1 + kn);
            rb[0] = *(const uint4*)(brow0 + kn);
            rb[1] = *(const uint4*)(brow1 + kn);
        }

        unsigned abase = sbase + buf * (2 * ATB);
        unsigned bbase = abase + ATB;
        #pragma unroll
        for (int s = 0; s < 2; s++) {
            int ks = s * 16;
            unsigned afr[4][4], bfr[4][2];
            #pragma unroll
            for (int mt = 0; mt < 4; mt++) {
                int m0 = wm0 + mt * 16;
                int row = m0 + rl + ((tl & 1) << 3);
                int col = ks + ((tl >> 1) << 3);
                ldsm4(afr[mt], abase + row * 80 + col * 2);
            }
            #pragma unroll
            for (int nb = 0; nb < 2; nb++) {
                int n0 = wn0 + nb * 16;
                int row = n0 + rl + ((tl >> 1) << 3);
                int col = ks + ((tl & 1) << 3);
                unsigned r4[4];
                ldsm4(r4, bbase + row * 80 + col * 2);
                bfr[nb * 2 + 0][0] = r4[0]; bfr[nb * 2 + 0][1] = r4[1];
                bfr[nb * 2 + 1][0] = r4[2]; bfr[nb * 2 + 1][1] = r4[3];
            }
            #pragma unroll
            for (int mt = 0; mt < 4; mt++)
                #pragma unroll
                for (int nt = 0; nt < 4; nt++)
                    mma_fp16(acc[mt * 4 + nt], afr[mt], bfr[nt]);
        }

        if (next) {
            char* d = sm[buf ^ 1];
            *(uint4*)(d + srow * 80 + sg * 16)              = ra[0];
            *(uint4*)(d + (srow + 64) * 80 + sg * 16)       = ra[1];
            *(uint4*)(d + ATB + srow * 80 + sg * 16)        = rb[0];
            *(uint4*)(d + ATB + (srow + 64) * 80 + sg * 16) = rb[1];
        }
        __syncthreads();
        buf ^= 1;
    }

    // ---- epilogue: uniform single-output paths, vectorized stores ----
    if (Cq) {
        #pragma unroll
        for (int mt = 0; mt < 4; mt++) {
            int r0 = row0 + wm0 + mt * 16 + mrow;
            #pragma unroll
            for (int nt = 0; nt < 4; nt++) {
                int gc = col0 + wn0 + nt * 8 + 2 * kr;
                const float* cc = acc[mt * 4 + nt];
                #pragma unroll
                for (int h = 0; h < 2; h++) {
                    int gr = r0 + h * 8;
                    float v0 = cc[h * 2 + 0], v1 = cc[h * 2 + 1];
                    if (bp) { v0 += bp[gc] * biasMul; v1 += bp[gc + 1] * biasMul; }
                    if (rowv) {
                        float rv = rowv[gr];
                        v0 += rv * colv[(long long)gc * cvs];
                        v1 += rv * colv[(long long)(gc + 1) * cvs];
                    }
                    v0 *= scale; v1 *= scale;
                    if (relu) { v0 = fmaxf(v0, 0.f); v1 = fmaxf(v1, 0.f); }
                    if (gc + 1 < N)
                        *(__half2*)(Cq + (long long)gr * ldc + gc) = __floats2half2_rn(v0, v1);
                    else if (gc < N)
                        Cq[(long long)gr * ldc + gc] = __float2half_rn(v0);
                }
            }
        }
    } else {
        bool al = (ldc & 1) == 0;
        #pragma unroll
        for (int mt = 0; mt < 4; mt++) {
            int r0 = row0 + wm0 + mt * 16 + mrow;
            #pragma unroll
            for (int nt = 0; nt < 4; nt++) {
                int gc = col0 + wn0 + nt * 8 + 2 * kr;
                const float* cc = acc[mt * 4 + nt];
                #pragma unroll
                for (int h = 0; h < 2; h++) {
                    int gr = r0 + h * 8;
                    float v0 = cc[h * 2 + 0], v1 = cc[h * 2 + 1];
                    if (bp) { v0 += bp[gc] * biasMul; v1 += bp[gc + 1] * biasMul; }
                    if (rowv) {
                        float rv = rowv[gr];
                        v0 += rv * colv[(long long)gc * cvs];
                        v1 += rv * colv[(long long)(gc + 1) * cvs];
                    }
                    v0 *= scale; v1 *= scale;
                    if (relu) { v0 = fmaxf(v0, 0.f); v1 = fmaxf(v1, 0.f); }
                    long long base = (long long)gr * ldc + gc;
                    if (al && gc + 1 < N) {
                        float2 o; o.x = v0; o.y = v1;
                        *(float2*)(Cp + base) = o;
                    } else {
                        if (gc < N) Cp[base] = v0;
                        if (gc + 1 < N) Cp[base + 1] = v1;
                    }
                }
            }
        }
    }
}

// ---------------- generic single-GEMM wrapper (z-batched) ----------------
__global__ void __launch_bounds__(256, 2) gemm_h5(
    const __half* __restrict__ A, int lda, long long sA,
    const __half* __restrict__ B, int ldb, long long sB,
    const float* __restrict__ bias, long long sBias, float biasMul,
    float* __restrict__ C, __half* __restrict__ C16, int ldc, long long sC,
    int M, int N, int K, float scale, int relu)
{
    int bz = blockIdx.z;
    const float* bp = bias ? bias + (long long)bz * sBias : (const float*)0;
    gemm_body(A + (long long)bz * sA, lda, B + (long long)bz * sB, ldb,
              bp, biasMul, (const float*)0, (const float*)0, 0,
              C ? C + (long long)bz * sC : (float*)0,
              C16 ? C16 + (long long)bz * sC : (__half*)0, ldc,
              blockIdx.y * 128, blockIdx.x * 128, N, K, scale, relu);
}

// ---------------- paired GEMM: z selects between two fp32-out descs ----------------
struct GD {
    const __half* A; int lda;
    const __half* B; int ldb;
    const float* bias;
    const float* rowv; const float* colv;
    float* C;
    int K;
};

__global__ void __launch_bounds__(256, 2) gemm_pair(GD g0, GD g1, int N, int ldc)
{
    const GD& g = (blockIdx.z == 0) ? g0 : g1;
    gemm_body(g.A, g.lda, g.B, g.ldb, g.bias, 1.f, g.rowv, g.colv, 1,
              g.C, (__half*)0, ldc,
              blockIdx.y * 128, blockIdx.x * 128, N, g.K, 1.f, 0);
}

// ---------------- fused weight prelude (all converts/packs in one launch) --------
#define PRE_W_TOT (196608 + 33024 + 131072 + 131072 + 98304 + 768 + 262144 + 1024 + 2097152 + 8192)

__global__ void prelude_w_k(
    const float* __restrict__ w_hh, const float* __restrict__ dec_w2,
    const float* __restrict__ msg_w, const float* __restrict__ aw2,
    const float* __restrict__ w_ih,
    const float* __restrict__ ew1, const float* __restrict__ eb1,
    const float* __restrict__ dw1, const float* __restrict__ db1,
    const float* __restrict__ aw1, const float* __restrict__ ab1,
    const float* __restrict__ cw1, const float* __restrict__ cb1,
    __half* __restrict__ whh16, __half* __restrict__ dw216,
    __half* __restrict__ msgw16, __half* __restrict__ aw216,
    __half* __restrict__ wih16, float* __restrict__ wihc,
    __half* __restrict__ pw16, float* __restrict__ pb,
    __half* __restrict__ pw216, float* __restrict__ pb2)
{
    long long i = (long long)blockIdx.x * 256 + threadIdx.x;
    if (i >= PRE_W_TOT) return;
    if (i < 196608) { whh16[i] = __float2half_rn(w_hh[i]); return; }
    i -= 196608;
    if (i < 33024) { dw216[i] = __float2half_rn(dec_w2[i]); return; }
    i -= 33024;
    if (i < 131072) { msgw16[i] = __float2half_rn(msg_w[i]); return; }
    i -= 131072;
    if (i < 131072) { aw216[i] = __float2half_rn(aw2[i]); return; }
    i -= 131072;
    if (i < 98304) {
        int r = (int)(i >> 7), c = (int)(i & 127);
        wih16[i] = __float2half_rn(w_ih[r * 129 + c]);
        return;
    }
    i -= 98304;
    if (i < 768) { wihc[i] = w_ih[i * 129 + 128]; return; }
    i -= 768;
    if (i < 262144) {
        int r = (int)(i >> 8), c = (int)(i & 255);
        float v;
        if (r < 256)      v = ew1[r * 512 + c];
        else if (r < 512) v = ew1[(r - 256) * 512 + 256 + c];
        else if (r < 768) v = dw1[(r - 512) * 512 + c];
        else              v = dw1[(r - 768) * 512 + 256 + c];
        pw16[i] = __float2half_rn(v);
        return;
    }
    i -= 262144;
    if (i < 1024) {
        int r = (int)i;
        float v = 0.f;
        if (r >= 256 && r < 512) v = eb1[r - 256];
        else if (r >= 768)       v = db1[r - 768];
        pb[r] = v;
        return;
    }
    i -= 1024;
    if (i < 2097152) {
        int n = (int)(i >> 17);
        int r = (int)((i >> 8) & 511);
        int c = (int)(i & 255);
        float v = (r < 256) ? aw1[n * 65536 + r * 256 + c]
                            : cw1[n * 65536 + (r - 256) * 256 + c];
        pw216[i] = __float2half_rn(v);
        return;
    }
    i -= 2097152;
    {
        int n = (int)(i >> 9), r = (int)(i & 511);
        pb2[i] = (r < 256) ? ab1[n * 256 + r] : cb1[n * 256 + r - 256];
    }
}

// ---------------- activation prelude: obs16 + h016 ----------------
__global__ void prelude_a_k(const float* __restrict__ obs, const float* __restrict__ h0,
                            __half* __restrict__ obs16, __half* __restrict__ h016)
{
    long long i4 = (long long)blockIdx.x * 256 + threadIdx.x;
    if (i4 >= (BN_ * 128 + BN_ * 256) / 4) return;
    const float* s;
    __half* d;
    long long off;
    if (i4 < BN_ * 128 / 4) { s = obs; d = obs16; off = i4 * 4; }
    else { s = h0; d = h016; off = (i4 - BN_ * 128 / 4) * 4; }
    float4 v = *(const float4*)(s + off);
    *(__half2*)(d + off)     = __floats2half2_rn(v.x, v.y);
    *(__half2*)(d + off + 2) = __floats2half2_rn(v.z, v.w);
}

// ---------------- GRU gates (float4), writes fp32 hidden + fp16 mirror ----------------
__global__ void gru_gate4_k(const float* __restrict__ gx, const float* __restrict__ gh,
                            const float* __restrict__ h0, float* __restrict__ h,
                            __half* __restrict__ h16)
{
    int idx = blockIdx.x * blockDim.x + threadIdx.x;  // over BN_*64
    if (idx >= BN_ * 64) return;
    int m = idx >> 6;
    int c4 = (idx & 63) * 4;
    long long bx = (long long)m * 768 + c4;
    float4 xr = *(const float4*)(gx + bx);
    float4 xz = *(const float4*)(gx + bx + 256);
    float4 xn = *(const float4*)(gx + bx + 512);
    float4 hr = *(const float4*)(gh + bx);
    float4 hz = *(const float4*)(gh + bx + 256);
    float4 hn = *(const float4*)(gh + bx + 512);
    float4 h0v = *(const float4*)(h0 + (long long)m * 256 + c4);
    float4 o;
    {
        float r = 1.f / (1.f + expf(-(xr.x + hr.x)));
        float z = 1.f / (1.f + expf(-(xz.x + hz.x)));
        float nc = tanhf(xn.x + r * hn.x);
        o.x = (1.f - z) * nc + z * h0v.x;
    }
    {
        float r = 1.f / (1.f + expf(-(xr.y + hr.y)));
        float z = 1.f / (1.f + expf(-(xz.y + hz.y)));
        float nc = tanhf(xn.y + r * hn.y);
        o.y = (1.f - z) * nc + z * h0v.y;
    }
    {
        float r = 1.f / (1.f + expf(-(xr.z + hr.z)));
        float z = 1.f / (1.f + expf(-(xz.z + hz.z)));
        float nc = tanhf(xn.z + r * hn.z);
        o.z = (1.f - z) * nc + z * h0v.z;
    }
    {
        float r = 1.f / (1.f + expf(-(xr.w + hr.w)));
        float z = 1.f / (1.f + expf(-(xz.w + hz.w)));
        float nc = tanhf(xn.w + r * hn.w);
        o.w = (1.f - z) * nc + z * h0v.w;
    }
    *(float4*)(h + (long long)m * 256 + c4) = o;
    *(__half2*)(h16 + (long long)m * 256 + c4)     = __floats2half2_rn(o.x, o.y);
    *(__half2*)(h16 + (long long)m * 256 + c4 + 2) = __floats2half2_rn(o.z, o.w);
}

// ---------------- fused per-batch edge kernel (fp16 node projections) ----------------
__global__ __launch_bounds__(256) void edge_k(
    const __half* __restrict__ node,         // [B*N, 1024]: eHs|eHr|dHs|dHr
    const float* __restrict__ w2, const float* __restrict__ b2,
    float* __restrict__ rel, __half* __restrict__ Sout)
{
    __shared__ float sW2[KK * SH];
    __shared__ float sS[Nn][SH];
    int b = blockIdx.x;
    int tid = threadIdx.x;
    for (int i = tid; i < KK * SH; i += 256) sW2[i] = w2[i];
    for (int i = tid; i < Nn * SH; i += 256) (&sS[0][0])[i] = 0.f;
    __syncthreads();

    int w = tid >> 5, lane = tid & 31;
    long long base = (long long)b * Nn * 1024;
    for (int ii = 0; ii < 2; ii++) {
        int i = w * 2 + ii;
        float eR[8], dR[8];
        #pragma unroll
        for (int q = 0; q < 8; q++) {
            int c = lane + 32 * q;
            eR[q] = __half2float(node[base + i * 1024 + 256 + c]);
            dR[q] = __half2float(node[base + i * 1024 + 768 + c]);
        }
        for (int j = 0; j < Nn; j++) {
            if (j == i) continue;
            float part[KK];
            #pragma unroll
            for (int k = 0; k < KK; k++) part[k] = 0.f;
            #pragma unroll
            for (int q = 0; q < 8; q++) {
                int c = lane + 32 * q;
                float pe = __half2float(node[base + j * 1024 + c]) + eR[q];
                pe = fmaxf(pe, 0.f);
                #pragma unroll
                for (int k = 0; k < KK; k++) part[k] += pe * sW2[k * SH + c];
                float pd = __half2float(node[base + j * 1024 + 512 + c]) + dR[q];
                pd = fmaxf(pd, 0.f);
                sS[i][c] += pd;
            }
            #pragma unroll
            for (int k = 0; k < KK; k++) {
                #pragma unroll
                for (int off = 16; off; off >>= 1)
                    part[k] += __shfl_xor_sync(0xffffffffu, part[k], off);
                part[k] += b2[k];
            }
            if (lane == 0) {
                float mx = part[0];
                #pragma unroll
                for (int k = 1; k < KK; k++) mx = fmaxf(mx, part[k]);
                float e_[KK], s = 0.f;
                #pragma unroll
                for (int k = 0; k < KK; k++) { e_[k] = expf(part[k] - mx); s += e_[k]; }
                float inv = 1.f / s;
                int jj = (j < i) ? j : j - 1;
                long long eo = ((long long)b * Ee + i * 15 + jj) * KK;
                #pragma unroll
                for (int k = 0; k < KK; k++) rel[eo + k] = e_[k] * inv;
            }
        }
    }
    __syncthreads();
    long long sb = (long long)b * Nn * SH;
    for (int i = tid; i < Nn * SH; i += 256)
        Sout[sb + i] = __float2half_rn((&sS[0][0])[i]);
}

// ---------------- message aggregation + build ai16 = [obs, message] ----------------
__global__ __launch_bounds__(256) void message_k(
    const float* __restrict__ rel, const __half* __restrict__ msgs,
    const __half* __restrict__ obs16, __half* __restrict__ ai16)
{
    __shared__ float sRel[Ee * KK];  // 1920
    int b = blockIdx.x;
    int tid = threadIdx.x;
    for (int i = tid; i < Ee * KK; i += 256) sRel[i] = rel[(long long)b * Ee * KK + i];
    __syncthreads();

    int d = tid & 127;
    int g = tid >> 7;
    float acc[8];
    #pragma unroll
    for (int ii = 0; ii < 8; ii++) acc[ii] = 0.f;
    long long mb = (long long)b * Nn * KK * OBS;
    for (int j = 0; j < Nn; j++) {
        float mj[KK];
        #pragma unroll
        for (int k = 0; k < KK; k++) mj[k] = __half2float(msgs[mb + (j * KK + k) * OBS + d]);
        #pragma unroll
        for (int ii = 0; ii < 8; ii++) {
            int i = g * 8 + ii;
            if (i == j) continue;
            int jj = (j < i) ? j : j - 1;
            const float* r = &sRel[(i * 15 + jj) * KK];
            float a = acc[ii];
            #pragma unroll
            for (int k = 0; k < KK; k++) a += r[k] * mj[k];
            acc[ii] = a;
        }
    }
    long long ab = (long long)b * Nn * 2 * OBS;
    #pragma unroll
    for (int ii = 0; ii < 8; ii++) {
        int i = g * 8 + ii;
        ai16[ab + i * 2 * OBS + OBS + d] = __float2half_rn(acc[ii]);
    }
    for (int idx = tid; idx < Nn * OBS; idx += 256) {
        int i = idx >> 7, dd = idx & 127;
        ai16[ab + i * 2 * OBS + dd] = obs16[(long long)b * Nn * OBS + idx];
    }
}

// ---------------- critic layer 2 (N=1): one warp per (b,n) dot ----------------
__global__ void critic2_k(const __half* __restrict__ h1, const float* __restrict__ w2,
                          const float* __restrict__ b2v, float* __restrict__ out)
{
    int w = (blockIdx.x * blockDim.x + threadIdx.x) >> 5;
    int lane = threadIdx.x & 31;
    if (w >= BN_) return;
    int n = w & 15;
    float s = 0.f;
    #pragma unroll
    for (int q = 0; q < 8; q++) {
        int c = lane + 32 * q;
        s += __half2float(h1[(long long)w * 512 + 256 + c]) * w2[n * 256 + c];
    }
    #pragma unroll
    for (int off = 16; off; off >>= 1) s += __shfl_xor_sync(0xffffffffu, s, off);
    if (lane == 0) out[w] = s + b2v[n];
}

// ---------------- launch ----------------
extern "C" void kernel_launch(void* const* d_in, const int* in_sizes, int n_in,
                              void* d_out, int out_size)
{
    const float* obs    = (const float*)d_in[0];
    const float* rew    = (const float*)d_in[1];
    const float* h0     = (const float*)d_in[2];
    const float* w_ih   = (const float*)d_in[3];
    const float* w_hh   = (const float*)d_in[4];
    const float* b_ih   = (const float*)d_in[5];
    const float* b_hh   = (const float*)d_in[6];
    const float* enc_w1 = (const float*)d_in[7];
    const float* enc_b1 = (const float*)d_in[8];
    const float* enc_w2 = (const float*)d_in[9];
    const float* enc_b2 = (const float*)d_in[10];
    const float* dec_w1 = (const float*)d_in[11];
    const float* dec_b1 = (const float*)d_in[12];
    const float* dec_w2 = (const float*)d_in[13];
    const float* dec_b2 = (const float*)d_in[14];
    const float* msg_w  = (const float*)d_in[15];
    const float* msg_b  = (const float*)d_in[16];
    const float* aw1    = (const float*)d_in[17];
    const float* ab1    = (const float*)d_in[18];
    const float* aw2    = (const float*)d_in[19];
    const float* ab2    = (const float*)d_in[20];
    const float* cw1    = (const float*)d_in[21];
    const float* cb1    = (const float*)d_in[22];
    const float* cw2    = (const float*)d_in[23];
    const float* cb2    = (const float*)d_in[24];
    float* out = (float*)d_out;

    float *pgx, *pgh, *pb, *pb2, *pwihc;
    __half *obs16, *h016, *hid16, *node16, *S16, *msgs16, *ai16, *h116;
    __half *wih16, *whh16, *pw16, *dw216, *msgw16, *pw216, *aw216;
    cudaGetSymbolAddress((void**)&pgx,    g_gx);
    cudaGetSymbolAddress((void**)&pgh,    g_gh);
    cudaGetSymbolAddress((void**)&pb,     g_pb);
    cudaGetSymbolAddress((void**)&pb2,    g_pb2);
    cudaGetSymbolAddress((void**)&pwihc,  g_wihc);
    cudaGetSymbolAddress((void**)&obs16,  g_obs16);
    cudaGetSymbolAddress((void**)&h016,   g_h016);
    cudaGetSymbolAddress((void**)&hid16,  g_hid16);
    cudaGetSymbolAddress((void**)&node16, g_node16);
    cudaGetSymbolAddress((void**)&S16,    g_S16);
    cudaGetSymbolAddress((void**)&msgs16, g_msgs16);
    cudaGetSymbolAddress((void**)&ai16,   g_ai16);
    cudaGetSymbolAddress((void**)&h116,   g_h116);
    cudaGetSymbolAddress((void**)&wih16,  g_wih16);
    cudaGetSymbolAddress((void**)&whh16,  g_whh16);
    cudaGetSymbolAddress((void**)&pw16,   g_pw16);
    cudaGetSymbolAddress((void**)&dw216,  g_dw216);
    cudaGetSymbolAddress((void**)&msgw16, g_msgw16);
    cudaGetSymbolAddress((void**)&pw216,  g_pw216);
    cudaGetSymbolAddress((void**)&aw216,  g_aw216);

    float* actor  = out;                 // [B,N,32]    524288
    float* critic = out + 524288;        // [B,N,1]     16384
    float* scm    = out + 540672;        // [B,N,129]   2113536
    float* rel    = out + 2654208;       // [B,E,8]     1966080
    float* hid    = out + 4620288;       // [1,B*N,256] 4194304

    const float* NF = (const float*)0;
    float* NC = (float*)0;
    __half* NH = (__half*)0;

    // 1-2: fused preludes
    prelude_w_k<<<(PRE_W_TOT + 255) / 256, 256>>>(
        w_hh, dec_w2, msg_w, aw2, w_ih,
        enc_w1, enc_b1, dec_w1, dec_b1, aw1, ab1, cw1, cb1,
        whh16, dw216, msgw16, aw216, wih16, pwihc, pw16, pb, pw216, pb2);
    prelude_a_k<<<((BN_ * 384 / 4) + 255) / 256, 256>>>(obs, h0, obs16, h016);

    // GRU: merged gx+gh in one launch (z=0: gx with rank-1 reward term; z=1: gh)
    {
        GD g0, g1;
        g0.A = obs16; g0.lda = 128; g0.B = wih16; g0.ldb = 128;
        g0.bias = b_ih; g0.rowv = rew; g0.colv = pwihc; g0.C = pgx; g0.K = 128;
        g1.A = h016; g1.lda = 256; g1.B = whh16; g1.ldb = 256;
        g1.bias = b_hh; g1.rowv = NF; g1.colv = NF; g1.C = pgh; g1.K = 256;
        gemm_pair<<<dim3(6, 128, 2), 256>>>(g0, g1, 768, 768);
    }
    gru_gate4_k<<<(BN_ * 64 + 255) / 256, 256>>>(pgx, pgh, h0, hid, hid16);

    // node projections [16384,1024] = hid @ pw^T + pb (fp16 out)
    gemm_h5<<<dim3(8, 128, 1), 256>>>(
        hid16, 256, 0, pw16, 256, 0, pb, 0, 1.f,
        NC, node16, 1024, 0, BN_, 1024, 256, 1.f, 0);

    edge_k<<<Bz, 256>>>(node16, enc_w2, enc_b2, rel, S16);

    // scm_pred = (S @ dec_w2^T + 15*b2) / 15.000001
    gemm_h5<<<dim3(2, 128, 1), 256>>>(
        S16, 256, 0, dw216, 256, 0, dec_b2, 0, 15.0f,
        scm, NH, 129, 0, BN_, 129, 256, 1.f / 15.000001f, 0);

    // msgs: [16384,1024] = obs @ msg_w^T + msg_b (fp16 out)
    gemm_h5<<<dim3(8, 128, 1), 256>>>(
        obs16, 128, 0, msgw16, 128, 0, msg_b, 0, 1.f,
        NC, msgs16, 1024, 0, BN_, 1024, 128, 1.f, 0);

    message_k<<<Bz, 256>>>(rel, msgs16, obs16, ai16);

    // fused actor+critic layer 1, batched over agent: [1024,512] per agent (fp16 out)
    gemm_h5<<<dim3(4, 8, 16), 256>>>(
        ai16, 4096, 256, pw216, 256, 512 * 256, pb2, 512, 1.f,
        NC, h116, 8192, 512, Bz, 512, 256, 1.f, 1);

    // actor layer 2 (N=32), batched over agent
    gemm_h5<<<dim3(1, 8, 16), 256>>>(
        h116, 8192, 512, aw216, 256, 32 * 256, ab2, 32, 1.f,
        actor, NH, 512, 32, Bz, 32, 256, 1.f, 0);

    critic2_k<<<BN_ / 8, 256>>>(h116, cw2, cb2, critic);
}

// round 14
// speedup vs baseline: 1.4144x; 1.0791x over previous
#include <cuda_runtime.h>
#include <cuda_fp16.h>
#include <math.h>
#include <string.h>

#define Bz   1024
#define Nn   16
#define OBS  128
#define ACTD 32
#define RH   256
#define SH   256
#define KK   8
#define Ee   240
#define BN_  (Bz*Nn)   // 16384

// ---------------- scratch (__device__ globals; no allocation) ----------------
__device__ float g_gx  [BN_*768];
__device__ float g_gh  [BN_*768];
__device__ float g_pb  [1024];
__device__ float g_pb2 [16*512];
__device__ float g_wihc[768];

__device__ __align__(256) __half g_obs16 [BN_*128];
__device__ __align__(256) __half g_h016  [BN_*256];
__device__ __align__(256) __half g_hid16 [BN_*256];
__device__ __align__(256) __half g_node16[BN_*1024];
__device__ __align__(256) __half g_S16   [BN_*256];
__device__ __align__(256) __half g_msgs16[BN_*1024];
__device__ __align__(256) __half g_ai16  [BN_*256];
__device__ __align__(256) __half g_h116  [BN_*512];
__device__ __align__(256) __half g_wih16 [768*128];
__device__ __align__(256) __half g_whh16 [768*256];
__device__ __align__(256) __half g_pw16  [1024*256];
__device__ __align__(256) __half g_dw216 [129*256];
__device__ __align__(256) __half g_msgw16[1024*128];
__device__ __align__(256) __half g_pw216 [16*512*256];
__device__ __align__(256) __half g_aw216 [16*32*256];

// ---------------- helpers ----------------
__device__ __forceinline__ unsigned smem_u32(const void* p) {
    unsigned a;
    asm("{ .reg .u64 t; cvta.to.shared.u64 t, %1; cvt.u32.u64 %0, t; }" : "=r"(a) : "l"(p));
    return a;
}

__device__ __forceinline__ void mma_fp16(float* c, const unsigned* a, const unsigned* b) {
    asm volatile(
        "mma.sync.aligned.m16n8k16.row.col.f32.f16.f16.f32 "
        "{%0,%1,%2,%3}, {%4,%5,%6,%7}, {%8,%9}, {%0,%1,%2,%3};"
        : "+f"(c[0]), "+f"(c[1]), "+f"(c[2]), "+f"(c[3])
        : "r"(a[0]), "r"(a[1]), "r"(a[2]), "r"(a[3]), "r"(b[0]), "r"(b[1]));
}

__device__ __forceinline__ void ldsm4(unsigned* r, unsigned addr) {
    asm volatile("ldmatrix.sync.aligned.m8n8.x4.shared.b16 {%0,%1,%2,%3}, [%4];"
                 : "=r"(r[0]), "=r"(r[1]), "=r"(r[2]), "=r"(r[3]) : "r"(addr));
}

// ---------------- GEMM body: 128x128 tile, BK=32, fp16 LDG staging, reg-prefetch DB
// out = (A@B^T + bias*biasMul + rowv*colv)*scale [,relu]; exactly one of Cp/Cq non-null.
#define ATB 10240   // 128 rows * 80 bytes

__device__ __forceinline__ void gemm_body(
    const __half* __restrict__ A, int lda,
    const __half* __restrict__ B, int ldb,
    const float* __restrict__ bp, float biasMul,
    const float* __restrict__ rowv, const float* __restrict__ colv, int cvs,
    float* __restrict__ Cp, __half* __restrict__ Cq, int ldc,
    int row0, int col0, int N, int K, float scale, int relu)
{
    __shared__ __align__(16) char sm[2][2 * ATB];   // [buf][A|B]

    int t = threadIdx.x;
    int wid = t >> 5, lane = t & 31;
    int wm0 = (wid & 1) * 64;        // 2 warps in M
    int wn0 = (wid >> 1) * 32;       // 4 warps in N
    int mrow = lane >> 2, kr = lane & 3;

    float acc[16][4];
    #pragma unroll
    for (int i = 0; i < 16; i++)
        #pragma unroll
        for (int j = 0; j < 4; j++) acc[i][j] = 0.f;

    int srow = t >> 2, sg = t & 3;
    uint4 ra[2], rb[2];
    const __half* arow0 = A + (long long)(row0 + srow) * lda + sg * 8;
    const __half* arow1 = A + (long long)(row0 + srow + 64) * lda + sg * 8;
    int gc0 = col0 + srow, gc1 = col0 + srow + 64;
    const __half* brow0 = B + (long long)((gc0 < N) ? gc0 : 0) * ldb + sg * 8;
    const __half* brow1 = B + (long long)((gc1 < N) ? gc1 : 0) * ldb + sg * 8;

    ra[0] = *(const uint4*)(arow0);
    ra[1] = *(const uint4*)(arow1);
    rb[0] = *(const uint4*)(brow0);
    rb[1] = *(const uint4*)(brow1);
    {
        char* d = sm[0];
        *(uint4*)(d + srow * 80 + sg * 16)              = ra[0];
        *(uint4*)(d + (srow + 64) * 80 + sg * 16)       = ra[1];
        *(uint4*)(d + ATB + srow * 80 + sg * 16)        = rb[0];
        *(uint4*)(d + ATB + (srow + 64) * 80 + sg * 16) = rb[1];
    }
    __syncthreads();

    unsigned sbase = smem_u32(sm);
    int buf = 0;
    int tl = lane >> 3, rl = lane & 7;
    for (int k0 = 0; k0 < K; k0 += 32) {
        bool next = (k0 + 32) < K;
        if (next) {
            int kn = k0 + 32;
            ra[0] = *(const uint4*)(arow0 + kn);
            ra[1] = *(const uint4*)(arow1 + kn);
            rb[0] = *(const uint4*)(brow0 + kn);
            rb[1] = *(const uint4*)(brow1 + kn);
        }

        unsigned abase = sbase + buf * (2 * ATB);
        unsigned bbase = abase + ATB;
        #pragma unroll
        for (int s = 0; s < 2; s++) {
            int ks = s * 16;
            unsigned afr[4][4], bfr[4][2];
            #pragma unroll
            for (int mt = 0; mt < 4; mt++) {
                int m0 = wm0 + mt * 16;
                int row = m0 + rl + ((tl & 1) << 3);
                int col = ks + ((tl >> 1) << 3);
                ldsm4(afr[mt], abase + row * 80 + col * 2);
            }
            #pragma unroll
            for (int nb = 0; nb < 2; nb++) {
                int n0 = wn0 + nb * 16;
                int row = n0 + rl + ((tl >> 1) << 3);
                int col = ks + ((tl & 1) << 3);
                unsigned r4[4];
                ldsm4(r4, bbase + row * 80 + col * 2);
                bfr[nb * 2 + 0][0] = r4[0]; bfr[nb * 2 + 0][1] = r4[1];
                bfr[nb * 2 + 1][0] = r4[2]; bfr[nb * 2 + 1][1] = r4[3];
            }
            #pragma unroll
            for (int mt = 0; mt < 4; mt++)
                #pragma unroll
                for (int nt = 0; nt < 4; nt++)
                    mma_fp16(acc[mt * 4 + nt], afr[mt], bfr[nt]);
        }

        if (next) {
            char* d = sm[buf ^ 1];
            *(uint4*)(d + srow * 80 + sg * 16)              = ra[0];
            *(uint4*)(d + (srow + 64) * 80 + sg * 16)       = ra[1];
            *(uint4*)(d + ATB + srow * 80 + sg * 16)        = rb[0];
            *(uint4*)(d + ATB + (srow + 64) * 80 + sg * 16) = rb[1];
        }
        __syncthreads();
        buf ^= 1;
    }

    // ---- epilogue: uniform single-output paths, vectorized stores ----
    if (Cq) {
        #pragma unroll
        for (int mt = 0; mt < 4; mt++) {
            int r0 = row0 + wm0 + mt * 16 + mrow;
            #pragma unroll
            for (int nt = 0; nt < 4; nt++) {
                int gc = col0 + wn0 + nt * 8 + 2 * kr;
                const float* cc = acc[mt * 4 + nt];
                #pragma unroll
                for (int h = 0; h < 2; h++) {
                    int gr = r0 + h * 8;
                    float v0 = cc[h * 2 + 0], v1 = cc[h * 2 + 1];
                    if (bp) { v0 += bp[gc] * biasMul; v1 += bp[gc + 1] * biasMul; }
                    if (rowv) {
                        float rv = rowv[gr];
                        v0 += rv * colv[(long long)gc * cvs];
                        v1 += rv * colv[(long long)(gc + 1) * cvs];
                    }
                    v0 *= scale; v1 *= scale;
                    if (relu) { v0 = fmaxf(v0, 0.f); v1 = fmaxf(v1, 0.f); }
                    if (gc + 1 < N)
                        *(__half2*)(Cq + (long long)gr * ldc + gc) = __floats2half2_rn(v0, v1);
                    else if (gc < N)
                        Cq[(long long)gr * ldc + gc] = __float2half_rn(v0);
                }
            }
        }
    } else {
        bool al = (ldc & 1) == 0;
        #pragma unroll
        for (int mt = 0; mt < 4; mt++) {
            int r0 = row0 + wm0 + mt * 16 + mrow;
            #pragma unroll
            for (int nt = 0; nt < 4; nt++) {
                int gc = col0 + wn0 + nt * 8 + 2 * kr;
                const float* cc = acc[mt * 4 + nt];
                #pragma unroll
                for (int h = 0; h < 2; h++) {
                    int gr = r0 + h * 8;
                    float v0 = cc[h * 2 + 0], v1 = cc[h * 2 + 1];
                    if (bp) { v0 += bp[gc] * biasMul; v1 += bp[gc + 1] * biasMul; }
                    if (rowv) {
                        float rv = rowv[gr];
                        v0 += rv * colv[(long long)gc * cvs];
                        v1 += rv * colv[(long long)(gc + 1) * cvs];
                    }
                    v0 *= scale; v1 *= scale;
                    if (relu) { v0 = fmaxf(v0, 0.f); v1 = fmaxf(v1, 0.f); }
                    long long base = (long long)gr * ldc + gc;
                    if (al && gc + 1 < N) {
                        float2 o; o.x = v0; o.y = v1;
                        *(float2*)(Cp + base) = o;
                    } else {
                        if (gc < N) Cp[base] = v0;
                        if (gc + 1 < N) Cp[base + 1] = v1;
                    }
                }
            }
        }
    }
}

// ---------------- generic single-GEMM wrapper (z-batched) ----------------
__global__ void __launch_bounds__(256, 2) gemm_h5(
    const __half* __restrict__ A, int lda, long long sA,
    const __half* __restrict__ B, int ldb, long long sB,
    const float* __restrict__ bias, long long sBias, float biasMul,
    float* __restrict__ C, __half* __restrict__ C16, int ldc, long long sC,
    int M, int N, int K, float scale, int relu)
{
    int bz = blockIdx.z;
    const float* bp = bias ? bias + (long long)bz * sBias : (const float*)0;
    gemm_body(A + (long long)bz * sA, lda, B + (long long)bz * sB, ldb,
              bp, biasMul, (const float*)0, (const float*)0, 0,
              C ? C + (long long)bz * sC : (float*)0,
              C16 ? C16 + (long long)bz * sC : (__half*)0, ldc,
              blockIdx.y * 128, blockIdx.x * 128, N, K, scale, relu);
}

// ---------------- paired GEMM descriptors ----------------
struct GD {
    const __half* A; int lda;
    const __half* B; int ldb;
    const float* bias;
    const float* rowv; const float* colv;
    float* C;
    int K;
};

__global__ void __launch_bounds__(256, 2) gemm_pair(GD g0, GD g1, int N, int ldc)
{
    const GD& g = (blockIdx.z == 0) ? g0 : g1;
    gemm_body(g.A, g.lda, g.B, g.ldb, g.bias, 1.f, g.rowv, g.colv, 1,
              g.C, (__half*)0, ldc,
              blockIdx.y * 128, blockIdx.x * 128, N, g.K, 1.f, 0);
}

// fp16-out pair (node projections + msgs)
struct GQ {
    const __half* A; int lda;
    const __half* B; int ldb;
    const float* bias;
    __half* Cq;
    int K;
};

__global__ void __launch_bounds__(256, 2) gemm_pairq(GQ g0, GQ g1, int N, int ldc)
{
    const GQ& g = (blockIdx.z == 0) ? g0 : g1;
    gemm_body(g.A, g.lda, g.B, g.ldb, g.bias, 1.f,
              (const float*)0, (const float*)0, 0,
              (float*)0, g.Cq, ldc,
              blockIdx.y * 128, blockIdx.x * 128, N, g.K, 1.f, 0);
}

// ---------------- fused weight prelude (all converts/packs in one launch) --------
#define PRE_W_TOT (196608 + 33024 + 131072 + 131072 + 98304 + 768 + 262144 + 1024 + 2097152 + 8192)

__global__ void prelude_w_k(
    const float* __restrict__ w_hh, const float* __restrict__ dec_w2,
    const float* __restrict__ msg_w, const float* __restrict__ aw2,
    const float* __restrict__ w_ih,
    const float* __restrict__ ew1, const float* __restrict__ eb1,
    const float* __restrict__ dw1, const float* __restrict__ db1,
    const float* __restrict__ aw1, const float* __restrict__ ab1,
    const float* __restrict__ cw1, const float* __restrict__ cb1,
    __half* __restrict__ whh16, __half* __restrict__ dw216,
    __half* __restrict__ msgw16, __half* __restrict__ aw216,
    __half* __restrict__ wih16, float* __restrict__ wihc,
    __half* __restrict__ pw16, float* __restrict__ pb,
    __half* __restrict__ pw216, float* __restrict__ pb2)
{
    long long i = (long long)blockIdx.x * 256 + threadIdx.x;
    if (i >= PRE_W_TOT) return;
    if (i < 196608) { whh16[i] = __float2half_rn(w_hh[i]); return; }
    i -= 196608;
    if (i < 33024) { dw216[i] = __float2half_rn(dec_w2[i]); return; }
    i -= 33024;
    if (i < 131072) { msgw16[i] = __float2half_rn(msg_w[i]); return; }
    i -= 131072;
    if (i < 131072) { aw216[i] = __float2half_rn(aw2[i]); return; }
    i -= 131072;
    if (i < 98304) {
        int r = (int)(i >> 7), c = (int)(i & 127);
        wih16[i] = __float2half_rn(w_ih[r * 129 + c]);
        return;
    }
    i -= 98304;
    if (i < 768) { wihc[i] = w_ih[i * 129 + 128]; return; }
    i -= 768;
    if (i < 262144) {
        int r = (int)(i >> 8), c = (int)(i & 255);
        float v;
        if (r < 256)      v = ew1[r * 512 + c];
        else if (r < 512) v = ew1[(r - 256) * 512 + 256 + c];
        else if (r < 768) v = dw1[(r - 512) * 512 + c];
        else              v = dw1[(r - 768) * 512 + 256 + c];
        pw16[i] = __float2half_rn(v);
        return;
    }
    i -= 262144;
    if (i < 1024) {
        int r = (int)i;
        float v = 0.f;
        if (r >= 256 && r < 512) v = eb1[r - 256];
        else if (r >= 768)       v = db1[r - 768];
        pb[r] = v;
        return;
    }
    i -= 1024;
    if (i < 2097152) {
        int n = (int)(i >> 17);
        int r = (int)((i >> 8) & 511);
        int c = (int)(i & 255);
        float v = (r < 256) ? aw1[n * 65536 + r * 256 + c]
                            : cw1[n * 65536 + (r - 256) * 256 + c];
        pw216[i] = __float2half_rn(v);
        return;
    }
    i -= 2097152;
    {
        int n = (int)(i >> 9), r = (int)(i & 511);
        pb2[i] = (r < 256) ? ab1[n * 256 + r] : cb1[n * 256 + r - 256];
    }
}

// ---------------- activation prelude: obs16 + h016 ----------------
__global__ void prelude_a_k(const float* __restrict__ obs, const float* __restrict__ h0,
                            __half* __restrict__ obs16, __half* __restrict__ h016)
{
    long long i4 = (long long)blockIdx.x * 256 + threadIdx.x;
    if (i4 >= (BN_ * 128 + BN_ * 256) / 4) return;
    const float* s;
    __half* d;
    long long off;
    if (i4 < BN_ * 128 / 4) { s = obs; d = obs16; off = i4 * 4; }
    else { s = h0; d = h016; off = (i4 - BN_ * 128 / 4) * 4; }
    float4 v = *(const float4*)(s + off);
    *(__half2*)(d + off)     = __floats2half2_rn(v.x, v.y);
    *(__half2*)(d + off + 2) = __floats2half2_rn(v.z, v.w);
}

// ---------------- GRU gates (float4), writes fp32 hidden + fp16 mirror ----------------
__global__ void gru_gate4_k(const float* __restrict__ gx, const float* __restrict__ gh,
                            const float* __restrict__ h0, float* __restrict__ h,
                            __half* __restrict__ h16)
{
    int idx = blockIdx.x * blockDim.x + threadIdx.x;  // over BN_*64
    if (idx >= BN_ * 64) return;
    int m = idx >> 6;
    int c4 = (idx & 63) * 4;
    long long bx = (long long)m * 768 + c4;
    float4 xr = *(const float4*)(gx + bx);
    float4 xz = *(const float4*)(gx + bx + 256);
    float4 xn = *(const float4*)(gx + bx + 512);
    float4 hr = *(const float4*)(gh + bx);
    float4 hz = *(const float4*)(gh + bx + 256);
    float4 hn = *(const float4*)(gh + bx + 512);
    float4 h0v = *(const float4*)(h0 + (long long)m * 256 + c4);
    float4 o;
    {
        float r = 1.f / (1.f + expf(-(xr.x + hr.x)));
        float z = 1.f / (1.f + expf(-(xz.x + hz.x)));
        float nc = tanhf(xn.x + r * hn.x);
        o.x = (1.f - z) * nc + z * h0v.x;
    }
    {
        float r = 1.f / (1.f + expf(-(xr.y + hr.y)));
        float z = 1.f / (1.f + expf(-(xz.y + hz.y)));
        float nc = tanhf(xn.y + r * hn.y);
        o.y = (1.f - z) * nc + z * h0v.y;
    }
    {
        float r = 1.f / (1.f + expf(-(xr.z + hr.z)));
        float z = 1.f / (1.f + expf(-(xz.z + hz.z)));
        float nc = tanhf(xn.z + r * hn.z);
        o.z = (1.f - z) * nc + z * h0v.z;
    }
    {
        float r = 1.f / (1.f + expf(-(xr.w + hr.w)));
        float z = 1.f / (1.f + expf(-(xz.w + hz.w)));
        float nc = tanhf(xn.w + r * hn.w);
        o.w = (1.f - z) * nc + z * h0v.w;
    }
    *(float4*)(h + (long long)m * 256 + c4) = o;
    *(__half2*)(h16 + (long long)m * 256 + c4)     = __floats2half2_rn(o.x, o.y);
    *(__half2*)(h16 + (long long)m * 256 + c4 + 2) = __floats2half2_rn(o.z, o.w);
}

// ---------------- edge kernel v2: register-resident w2, register dec accumulator ----
__global__ __launch_bounds__(256) void edge_k(
    const __half* __restrict__ node,         // [B*N, 1024]: eHs|eHr|dHs|dHr
    const float* __restrict__ w2, const float* __restrict__ b2,
    float* __restrict__ rel, __half* __restrict__ Sout)
{
    int b = blockIdx.x;
    int tid = threadIdx.x;
    int w = tid >> 5, lane = tid & 31;

    // enc_w2 in registers: wreg[q][k] = w2[k*SH + lane + 32q]
    float wreg[8][KK];
    #pragma unroll
    for (int q = 0; q < 8; q++)
        #pragma unroll
        for (int k = 0; k < KK; k++)
            wreg[q][k] = w2[k * SH + lane + 32 * q];

    long long base = (long long)b * Nn * 1024;
    for (int ii = 0; ii < 2; ii++) {
        int i = w * 2 + ii;
        float eR[8], dR[8], accD[8];
        #pragma unroll
        for (int q = 0; q < 8; q++) {
            int c = lane + 32 * q;
            eR[q] = __half2float(node[base + i * 1024 + 256 + c]);
            dR[q] = __half2float(node[base + i * 1024 + 768 + c]);
            accD[q] = 0.f;
        }
        for (int j = 0; j < Nn; j++) {
            if (j == i) continue;
            float part[KK];
            #pragma unroll
            for (int k = 0; k < KK; k++) part[k] = 0.f;
            #pragma unroll
            for (int q = 0; q < 8; q++) {
                int c = lane + 32 * q;
                float pe = __half2float(node[base + j * 1024 + c]) + eR[q];
                pe = fmaxf(pe, 0.f);
                #pragma unroll
                for (int k = 0; k < KK; k++) part[k] += pe * wreg[q][k];
                float pd = __half2float(node[base + j * 1024 + 512 + c]) + dR[q];
                accD[q] += fmaxf(pd, 0.f);
            }
            #pragma unroll
            for (int k = 0; k < KK; k++) {
                #pragma unroll
                for (int off = 16; off; off >>= 1)
                    part[k] += __shfl_xor_sync(0xffffffffu, part[k], off);
                part[k] += b2[k];
            }
            if (lane == 0) {
                float mx = part[0];
                #pragma unroll
                for (int k = 1; k < KK; k++) mx = fmaxf(mx, part[k]);
                float e_[KK], s = 0.f;
                #pragma unroll
                for (int k = 0; k < KK; k++) { e_[k] = expf(part[k] - mx); s += e_[k]; }
                float inv = 1.f / s;
                int jj = (j < i) ? j : j - 1;
                long long eo = ((long long)b * Ee + i * 15 + jj) * KK;
                #pragma unroll
                for (int k = 0; k < KK; k++) rel[eo + k] = e_[k] * inv;
            }
        }
        long long sb = (long long)b * Nn * SH + (long long)i * SH;
        #pragma unroll
        for (int q = 0; q < 8; q++)
            Sout[sb + lane + 32 * q] = __float2half_rn(accD[q]);
    }
}

// ---------------- message aggregation + build ai16 = [obs, message] ----------------
__global__ __launch_bounds__(256) void message_k(
    const float* __restrict__ rel, const __half* __restrict__ msgs,
    const __half* __restrict__ obs16, __half* __restrict__ ai16)
{
    __shared__ float sRel[Ee * KK];  // 1920
    int b = blockIdx.x;
    int tid = threadIdx.x;
    for (int i = tid; i < Ee * KK; i += 256) sRel[i] = rel[(long long)b * Ee * KK + i];
    __syncthreads();

    int d = tid & 127;
    int g = tid >> 7;
    float acc[8];
    #pragma unroll
    for (int ii = 0; ii < 8; ii++) acc[ii] = 0.f;
    long long mb = (long long)b * Nn * KK * OBS;
    for (int j = 0; j < Nn; j++) {
        float mj[KK];
        #pragma unroll
        for (int k = 0; k < KK; k++) mj[k] = __half2float(msgs[mb + (j * KK + k) * OBS + d]);
        #pragma unroll
        for (int ii = 0; ii < 8; ii++) {
            int i = g * 8 + ii;
            if (i == j) continue;
            int jj = (j < i) ? j : j - 1;
            const float* r = &sRel[(i * 15 + jj) * KK];
            float a = acc[ii];
            #pragma unroll
            for (int k = 0; k < KK; k++) a += r[k] * mj[k];
            acc[ii] = a;
        }
    }
    long long ab = (long long)b * Nn * 2 * OBS;
    #pragma unroll
    for (int ii = 0; ii < 8; ii++) {
        int i = g * 8 + ii;
        ai16[ab + i * 2 * OBS + OBS + d] = __float2half_rn(acc[ii]);
    }
    for (int idx = tid; idx < Nn * OBS; idx += 256) {
        int i = idx >> 7, dd = idx & 127;
        ai16[ab + i * 2 * OBS + dd] = obs16[(long long)b * Nn * OBS + idx];
    }
}

// ---------------- critic layer 2 (N=1): one warp per (b,n) dot ----------------
__global__ void critic2_k(const __half* __restrict__ h1, const float* __restrict__ w2,
                          const float* __restrict__ b2v, float* __restrict__ out)
{
    int w = (blockIdx.x * blockDim.x + threadIdx.x) >> 5;
    int lane = threadIdx.x & 31;
    if (w >= BN_) return;
    int n = w & 15;
    float s = 0.f;
    #pragma unroll
    for (int q = 0; q < 8; q++) {
        int c = lane + 32 * q;
        s += __half2float(h1[(long long)w * 512 + 256 + c]) * w2[n * 256 + c];
    }
    #pragma unroll
    for (int off = 16; off; off >>= 1) s += __shfl_xor_sync(0xffffffffu, s, off);
    if (lane == 0) out[w] = s + b2v[n];
}

// ---------------- launch ----------------
extern "C" void kernel_launch(void* const* d_in, const int* in_sizes, int n_in,
                              void* d_out, int out_size)
{
    const float* obs    = (const float*)d_in[0];
    const float* rew    = (const float*)d_in[1];
    const float* h0     = (const float*)d_in[2];
    const float* w_ih   = (const float*)d_in[3];
    const float* w_hh   = (const float*)d_in[4];
    const float* b_ih   = (const float*)d_in[5];
    const float* b_hh   = (const float*)d_in[6];
    const float* enc_w1 = (const float*)d_in[7];
    const float* enc_b1 = (const float*)d_in[8];
    const float* enc_w2 = (const float*)d_in[9];
    const float* enc_b2 = (const float*)d_in[10];
    const float* dec_w1 = (const float*)d_in[11];
    const float* dec_b1 = (const float*)d_in[12];
    const float* dec_w2 = (const float*)d_in[13];
    const float* dec_b2 = (const float*)d_in[14];
    const float* msg_w  = (const float*)d_in[15];
    const float* msg_b  = (const float*)d_in[16];
    const float* aw1    = (const float*)d_in[17];
    const float* ab1    = (const float*)d_in[18];
    const float* aw2    = (const float*)d_in[19];
    const float* ab2    = (const float*)d_in[20];
    const float* cw1    = (const float*)d_in[21];
    const float* cb1    = (const float*)d_in[22];
    const float* cw2    = (const float*)d_in[23];
    const float* cb2    = (const float*)d_in[24];
    float* out = (float*)d_out;

    float *pgx, *pgh, *pb, *pb2, *pwihc;
    __half *obs16, *h016, *hid16, *node16, *S16, *msgs16, *ai16, *h116;
    __half *wih16, *whh16, *pw16, *dw216, *msgw16, *pw216, *aw216;
    cudaGetSymbolAddress((void**)&pgx,    g_gx);
    cudaGetSymbolAddress((void**)&pgh,    g_gh);
    cudaGetSymbolAddress((void**)&pb,     g_pb);
    cudaGetSymbolAddress((void**)&pb2,    g_pb2);
    cudaGetSymbolAddress((void**)&pwihc,  g_wihc);
    cudaGetSymbolAddress((void**)&obs16,  g_obs16);
    cudaGetSymbolAddress((void**)&h016,   g_h016);
    cudaGetSymbolAddress((void**)&hid16,  g_hid16);
    cudaGetSymbolAddress((void**)&node16, g_node16);
    cudaGetSymbolAddress((void**)&S16,    g_S16);
    cudaGetSymbolAddress((void**)&msgs16, g_msgs16);
    cudaGetSymbolAddress((void**)&ai16,   g_ai16);
    cudaGetSymbolAddress((void**)&h116,   g_h116);
    cudaGetSymbolAddress((void**)&wih16,  g_wih16);
    cudaGetSymbolAddress((void**)&whh16,  g_whh16);
    cudaGetSymbolAddress((void**)&pw16,   g_pw16);
    cudaGetSymbolAddress((void**)&dw216,  g_dw216);
    cudaGetSymbolAddress((void**)&msgw16, g_msgw16);
    cudaGetSymbolAddress((void**)&pw216,  g_pw216);
    cudaGetSymbolAddress((void**)&aw216,  g_aw216);

    float* actor  = out;                 // [B,N,32]    524288
    float* critic = out + 524288;        // [B,N,1]     16384
    float* scm    = out + 540672;        // [B,N,129]   2113536
    float* rel    = out + 2654208;       // [B,E,8]     1966080
    float* hid    = out + 4620288;       // [1,B*N,256] 4194304

    const float* NF = (const float*)0;
    float* NC = (float*)0;
    __half* NH = (__half*)0;

    // 1-2: fused preludes
    prelude_w_k<<<(PRE_W_TOT + 255) / 256, 256>>>(
        w_hh, dec_w2, msg_w, aw2, w_ih,
        enc_w1, enc_b1, dec_w1, dec_b1, aw1, ab1, cw1, cb1,
        whh16, dw216, msgw16, aw216, wih16, pwihc, pw16, pb, pw216, pb2);
    prelude_a_k<<<((BN_ * 384 / 4) + 255) / 256, 256>>>(obs, h0, obs16, h016);

    // GRU: merged gx+gh in one launch (z=0: gx with rank-1 reward term; z=1: gh)
    {
        GD g0, g1;
        g0.A = obs16; g0.lda = 128; g0.B = wih16; g0.ldb = 128;
        g0.bias = b_ih; g0.rowv = rew; g0.colv = pwihc; g0.C = pgx; g0.K = 128;
        g1.A = h016; g1.lda = 256; g1.B = whh16; g1.ldb = 256;
        g1.bias = b_hh; g1.rowv = NF; g1.colv = NF; g1.C = pgh; g1.K = 256;
        gemm_pair<<<dim3(6, 128, 2), 256>>>(g0, g1, 768, 768);
    }
    gru_gate4_k<<<(BN_ * 64 + 255) / 256, 256>>>(pgx, pgh, h0, hid, hid16);

    // merged node projections + msgs (both [16384,1024] fp16 out)
    {
        GQ q0, q1;
        q0.A = hid16; q0.lda = 256; q0.B = pw16;   q0.ldb = 256;
        q0.bias = pb;    q0.Cq = node16; q0.K = 256;
        q1.A = obs16; q1.lda = 128; q1.B = msgw16; q1.ldb = 128;
        q1.bias = msg_b; q1.Cq = msgs16; q1.K = 128;
        gemm_pairq<<<dim3(8, 128, 2), 256>>>(q0, q1, 1024, 1024);
    }

    edge_k<<<Bz, 256>>>(node16, enc_w2, enc_b2, rel, S16);

    // scm_pred = (S @ dec_w2^T + 15*b2) / 15.000001
    gemm_h5<<<dim3(2, 128, 1), 256>>>(
        S16, 256, 0, dw216, 256, 0, dec_b2, 0, 15.0f,
        scm, NH, 129, 0, BN_, 129, 256, 1.f / 15.000001f, 0);

    message_k<<<Bz, 256>>>(rel, msgs16, obs16, ai16);

    // fused actor+critic layer 1, batched over agent: [1024,512] per agent (fp16 out)
    gemm_h5<<<dim3(4, 8, 16), 256>>>(
        ai16, 4096, 256, pw216, 256, 512 * 256, pb2, 512, 1.f,
        NC, h116, 8192, 512, Bz, 512, 256, 1.f, 1);

    // actor layer 2 (N=32), batched over agent
    gemm_h5<<<dim3(1, 8, 16), 256>>>(
        h116, 8192, 512, aw216, 256, 32 * 256, ab2, 32, 1.f,
        actor, NH, 512, 32, Bz, 32, 256, 1.f, 0);

    critic2_k<<<BN_ / 8, 256>>>(h116, cw2, cb2, critic);
}

// round 15
// speedup vs baseline: 1.4285x; 1.0100x over previous
#include <cuda_runtime.h>
#include <cuda_fp16.h>
#include <math.h>
#include <string.h>

#define Bz   1024
#define Nn   16
#define OBS  128
#define ACTD 32
#define RH   256
#define SH   256
#define KK   8
#define Ee   240
#define BN_  (Bz*Nn)   // 16384

// ---------------- scratch (__device__ globals; no allocation) ----------------
__device__ float g_gx  [BN_*768];
__device__ float g_gh  [BN_*768];
__device__ float g_pb  [1024];
__device__ float g_pb2 [16*512];
__device__ float g_wihc[768];

__device__ __align__(256) __half g_obs16 [BN_*128];
__device__ __align__(256) __half g_h016  [BN_*256];
__device__ __align__(256) __half g_hid16 [BN_*256];
__device__ __align__(256) __half g_node16[BN_*1024];
__device__ __align__(256) __half g_S16   [BN_*256];
__device__ __align__(256) __half g_msgs16[BN_*1024];
__device__ __align__(256) __half g_ai16  [BN_*256];
__device__ __align__(256) __half g_h116  [BN_*512];
__device__ __align__(256) __half g_wih16 [768*128];
__device__ __align__(256) __half g_whh16 [768*256];
__device__ __align__(256) __half g_pw16  [1024*256];
__device__ __align__(256) __half g_dw216 [129*256];
__device__ __align__(256) __half g_msgw16[1024*128];
__device__ __align__(256) __half g_pw216 [16*512*256];
__device__ __align__(256) __half g_aw216 [16*32*256];

// ---------------- helpers ----------------
__device__ __forceinline__ unsigned smem_u32(const void* p) {
    unsigned a;
    asm("{ .reg .u64 t; cvta.to.shared.u64 t, %1; cvt.u32.u64 %0, t; }" : "=r"(a) : "l"(p));
    return a;
}

__device__ __forceinline__ void mma_fp16(float* c, const unsigned* a, const unsigned* b) {
    asm volatile(
        "mma.sync.aligned.m16n8k16.row.col.f32.f16.f16.f32 "
        "{%0,%1,%2,%3}, {%4,%5,%6,%7}, {%8,%9}, {%0,%1,%2,%3};"
        : "+f"(c[0]), "+f"(c[1]), "+f"(c[2]), "+f"(c[3])
        : "r"(a[0]), "r"(a[1]), "r"(a[2]), "r"(a[3]), "r"(b[0]), "r"(b[1]));
}

__device__ __forceinline__ void ldsm4(unsigned* r, unsigned addr) {
    asm volatile("ldmatrix.sync.aligned.m8n8.x4.shared.b16 {%0,%1,%2,%3}, [%4];"
                 : "=r"(r[0]), "=r"(r[1]), "=r"(r[2]), "=r"(r[3]) : "r"(addr));
}

// ---------------- GEMM body: 128x128 tile, BK=32, fp16 LDG staging, reg-prefetch DB
#define ATB 10240   // 128 rows * 80 bytes

__device__ __forceinline__ void gemm_body(
    const __half* __restrict__ A, int lda,
    const __half* __restrict__ B, int ldb,
    const float* __restrict__ bp, float biasMul,
    const float* __restrict__ rowv, const float* __restrict__ colv, int cvs,
    float* __restrict__ Cp, __half* __restrict__ Cq, int ldc,
    int row0, int col0, int N, int K, float scale, int relu)
{
    __shared__ __align__(16) char sm[2][2 * ATB];   // [buf][A|B]

    int t = threadIdx.x;
    int wid = t >> 5, lane = t & 31;
    int wm0 = (wid & 1) * 64;
    int wn0 = (wid >> 1) * 32;
    int mrow = lane >> 2, kr = lane & 3;

    float acc[16][4];
    #pragma unroll
    for (int i = 0; i < 16; i++)
        #pragma unroll
        for (int j = 0; j < 4; j++) acc[i][j] = 0.f;

    int srow = t >> 2, sg = t & 3;
    uint4 ra[2], rb[2];
    const __half* arow0 = A + (long long)(row0 + srow) * lda + sg * 8;
    const __half* arow1 = A + (long long)(row0 + srow + 64) * lda + sg * 8;
    int gc0 = col0 + srow, gc1 = col0 + srow + 64;
    const __half* brow0 = B + (long long)((gc0 < N) ? gc0 : 0) * ldb + sg * 8;
    const __half* brow1 = B + (long long)((gc1 < N) ? gc1 : 0) * ldb + sg * 8;

    ra[0] = *(const uint4*)(arow0);
    ra[1] = *(const uint4*)(arow1);
    rb[0] = *(const uint4*)(brow0);
    rb[1] = *(const uint4*)(brow1);
    {
        char* d = sm[0];
        *(uint4*)(d + srow * 80 + sg * 16)              = ra[0];
        *(uint4*)(d + (srow + 64) * 80 + sg * 16)       = ra[1];
        *(uint4*)(d + ATB + srow * 80 + sg * 16)        = rb[0];
        *(uint4*)(d + ATB + (srow + 64) * 80 + sg * 16) = rb[1];
    }
    __syncthreads();

    unsigned sbase = smem_u32(sm);
    int buf = 0;
    int tl = lane >> 3, rl = lane & 7;
    for (int k0 = 0; k0 < K; k0 += 32) {
        bool next = (k0 + 32) < K;
        if (next) {
            int kn = k0 + 32;
            ra[0] = *(const uint4*)(arow0 + kn);
            ra[1] = *(const uint4*)(arow1 + kn);
            rb[0] = *(const uint4*)(brow0 + kn);
            rb[1] = *(const uint4*)(brow1 + kn);
        }

        unsigned abase = sbase + buf * (2 * ATB);
        unsigned bbase = abase + ATB;
        #pragma unroll
        for (int s = 0; s < 2; s++) {
            int ks = s * 16;
            unsigned afr[4][4], bfr[4][2];
            #pragma unroll
            for (int mt = 0; mt < 4; mt++) {
                int m0 = wm0 + mt * 16;
                int row = m0 + rl + ((tl & 1) << 3);
                int col = ks + ((tl >> 1) << 3);
                ldsm4(afr[mt], abase + row * 80 + col * 2);
            }
            #pragma unroll
            for (int nb = 0; nb < 2; nb++) {
                int n0 = wn0 + nb * 16;
                int row = n0 + rl + ((tl >> 1) << 3);
                int col = ks + ((tl & 1) << 3);
                unsigned r4[4];
                ldsm4(r4, bbase + row * 80 + col * 2);
                bfr[nb * 2 + 0][0] = r4[0]; bfr[nb * 2 + 0][1] = r4[1];
                bfr[nb * 2 + 1][0] = r4[2]; bfr[nb * 2 + 1][1] = r4[3];
            }
            #pragma unroll
            for (int mt = 0; mt < 4; mt++)
                #pragma unroll
                for (int nt = 0; nt < 4; nt++)
                    mma_fp16(acc[mt * 4 + nt], afr[mt], bfr[nt]);
        }

        if (next) {
            char* d = sm[buf ^ 1];
            *(uint4*)(d + srow * 80 + sg * 16)              = ra[0];
            *(uint4*)(d + (srow + 64) * 80 + sg * 16)       = ra[1];
            *(uint4*)(d + ATB + srow * 80 + sg * 16)        = rb[0];
            *(uint4*)(d + ATB + (srow + 64) * 80 + sg * 16) = rb[1];
        }
        __syncthreads();
        buf ^= 1;
    }

    // ---- epilogue: uniform single-output paths, vectorized stores ----
    if (Cq) {
        #pragma unroll
        for (int mt = 0; mt < 4; mt++) {
            int r0 = row0 + wm0 + mt * 16 + mrow;
            #pragma unroll
            for (int nt = 0; nt < 4; nt++) {
                int gc = col0 + wn0 + nt * 8 + 2 * kr;
                const float* cc = acc[mt * 4 + nt];
                #pragma unroll
                for (int h = 0; h < 2; h++) {
                    int gr = r0 + h * 8;
                    float v0 = cc[h * 2 + 0], v1 = cc[h * 2 + 1];
                    if (bp) { v0 += bp[gc] * biasMul; v1 += bp[gc + 1] * biasMul; }
                    if (rowv) {
                        float rv = rowv[gr];
                        v0 += rv * colv[(long long)gc * cvs];
                        v1 += rv * colv[(long long)(gc + 1) * cvs];
                    }
                    v0 *= scale; v1 *= scale;
                    if (relu) { v0 = fmaxf(v0, 0.f); v1 = fmaxf(v1, 0.f); }
                    if (gc + 1 < N)
                        *(__half2*)(Cq + (long long)gr * ldc + gc) = __floats2half2_rn(v0, v1);
                    else if (gc < N)
                        Cq[(long long)gr * ldc + gc] = __float2half_rn(v0);
                }
            }
        }
    } else {
        bool al = (ldc & 1) == 0;
        #pragma unroll
        for (int mt = 0; mt < 4; mt++) {
            int r0 = row0 + wm0 + mt * 16 + mrow;
            #pragma unroll
            for (int nt = 0; nt < 4; nt++) {
                int gc = col0 + wn0 + nt * 8 + 2 * kr;
                const float* cc = acc[mt * 4 + nt];
                #pragma unroll
                for (int h = 0; h < 2; h++) {
                    int gr = r0 + h * 8;
                    float v0 = cc[h * 2 + 0], v1 = cc[h * 2 + 1];
                    if (bp) { v0 += bp[gc] * biasMul; v1 += bp[gc + 1] * biasMul; }
                    if (rowv) {
                        float rv = rowv[gr];
                        v0 += rv * colv[(long long)gc * cvs];
                        v1 += rv * colv[(long long)(gc + 1) * cvs];
                    }
                    v0 *= scale; v1 *= scale;
                    if (relu) { v0 = fmaxf(v0, 0.f); v1 = fmaxf(v1, 0.f); }
                    long long base = (long long)gr * ldc + gc;
                    if (al && gc + 1 < N) {
                        float2 o; o.x = v0; o.y = v1;
                        *(float2*)(Cp + base) = o;
                    } else {
                        if (gc < N) Cp[base] = v0;
                        if (gc + 1 < N) Cp[base + 1] = v1;
                    }
                }
            }
        }
    }
}

// ---------------- generic single-GEMM wrapper (z-batched) ----------------
__global__ void __launch_bounds__(256, 2) gemm_h5(
    const __half* __restrict__ A, int lda, long long sA,
    const __half* __restrict__ B, int ldb, long long sB,
    const float* __restrict__ bias, long long sBias, float biasMul,
    float* __restrict__ C, __half* __restrict__ C16, int ldc, long long sC,
    int M, int N, int K, float scale, int relu)
{
    int bz = blockIdx.z;
    const float* bp = bias ? bias + (long long)bz * sBias : (const float*)0;
    gemm_body(A + (long long)bz * sA, lda, B + (long long)bz * sB, ldb,
              bp, biasMul, (const float*)0, (const float*)0, 0,
              C ? C + (long long)bz * sC : (float*)0,
              C16 ? C16 + (long long)bz * sC : (__half*)0, ldc,
              blockIdx.y * 128, blockIdx.x * 128, N, K, scale, relu);
}

// ---------------- paired GEMM descriptors ----------------
struct GD {
    const __half* A; int lda;
    const __half* B; int ldb;
    const float* bias;
    const float* rowv; const float* colv;
    float* C;
    int K;
};

__global__ void __launch_bounds__(256, 2) gemm_pair(GD g0, GD g1, int N, int ldc)
{
    const GD& g = (blockIdx.z == 0) ? g0 : g1;
    gemm_body(g.A, g.lda, g.B, g.ldb, g.bias, 1.f, g.rowv, g.colv, 1,
              g.C, (__half*)0, ldc,
              blockIdx.y * 128, blockIdx.x * 128, N, g.K, 1.f, 0);
}

// fp16-out pair (node projections + msgs)
struct GQ {
    const __half* A; int lda;
    const __half* B; int ldb;
    const float* bias;
    __half* Cq;
    int K;
};

__global__ void __launch_bounds__(256, 2) gemm_pairq(GQ g0, GQ g1, int N, int ldc)
{
    const GQ& g = (blockIdx.z == 0) ? g0 : g1;
    gemm_body(g.A, g.lda, g.B, g.ldb, g.bias, 1.f,
              (const float*)0, (const float*)0, 0,
              (float*)0, g.Cq, ldc,
              blockIdx.y * 128, blockIdx.x * 128, N, g.K, 1.f, 0);
}

// ---------------- fused prelude (weights + activations in one launch) --------
#define PRE_W_TOT (196608 + 33024 + 131072 + 131072 + 98304 + 768 + 262144 + 1024 + 2097152 + 8192)
#define PRE_A_TOT ((BN_ * 128 + BN_ * 256) / 4)
#define PRE_TOT   (PRE_W_TOT + PRE_A_TOT)

__global__ void prelude_k(
    const float* __restrict__ w_hh, const float* __restrict__ dec_w2,
    const float* __restrict__ msg_w, const float* __restrict__ aw2,
    const float* __restrict__ w_ih,
    const float* __restrict__ ew1, const float* __restrict__ eb1,
    const float* __restrict__ dw1, const float* __restrict__ db1,
    const float* __restrict__ aw1, const float* __restrict__ ab1,
    const float* __restrict__ cw1, const float* __restrict__ cb1,
    const float* __restrict__ obs, const float* __restrict__ h0,
    __half* __restrict__ whh16, __half* __restrict__ dw216,
    __half* __restrict__ msgw16, __half* __restrict__ aw216,
    __half* __restrict__ wih16, float* __restrict__ wihc,
    __half* __restrict__ pw16, float* __restrict__ pb,
    __half* __restrict__ pw216, float* __restrict__ pb2,
    __half* __restrict__ obs16, __half* __restrict__ h016)
{
    long long i = (long long)blockIdx.x * 256 + threadIdx.x;
    if (i >= PRE_TOT) return;
    if (i >= PRE_W_TOT) {
        // activation section (float4 -> 2x half2)
        long long i4 = i - PRE_W_TOT;
        const float* s;
        __half* d;
        long long off;
        if (i4 < BN_ * 128 / 4) { s = obs; d = obs16; off = i4 * 4; }
        else { s = h0; d = h016; off = (i4 - BN_ * 128 / 4) * 4; }
        float4 v = *(const float4*)(s + off);
        *(__half2*)(d + off)     = __floats2half2_rn(v.x, v.y);
        *(__half2*)(d + off + 2) = __floats2half2_rn(v.z, v.w);
        return;
    }
    if (i < 196608) { whh16[i] = __float2half_rn(w_hh[i]); return; }
    i -= 196608;
    if (i < 33024) { dw216[i] = __float2half_rn(dec_w2[i]); return; }
    i -= 33024;
    if (i < 131072) { msgw16[i] = __float2half_rn(msg_w[i]); return; }
    i -= 131072;
    if (i < 131072) { aw216[i] = __float2half_rn(aw2[i]); return; }
    i -= 131072;
    if (i < 98304) {
        int r = (int)(i >> 7), c = (int)(i & 127);
        wih16[i] = __float2half_rn(w_ih[r * 129 + c]);
        return;
    }
    i -= 98304;
    if (i < 768) { wihc[i] = w_ih[i * 129 + 128]; return; }
    i -= 768;
    if (i < 262144) {
        int r = (int)(i >> 8), c = (int)(i & 255);
        float v;
        if (r < 256)      v = ew1[r * 512 + c];
        else if (r < 512) v = ew1[(r - 256) * 512 + 256 + c];
        else if (r < 768) v = dw1[(r - 512) * 512 + c];
        else              v = dw1[(r - 768) * 512 + 256 + c];
        pw16[i] = __float2half_rn(v);
        return;
    }
    i -= 262144;
    if (i < 1024) {
        int r = (int)i;
        float v = 0.f;
        if (r >= 256 && r < 512) v = eb1[r - 256];
        else if (r >= 768)       v = db1[r - 768];
        pb[r] = v;
        return;
    }
    i -= 1024;
    if (i < 2097152) {
        int n = (int)(i >> 17);
        int r = (int)((i >> 8) & 511);
        int c = (int)(i & 255);
        float v = (r < 256) ? aw1[n * 65536 + r * 256 + c]
                            : cw1[n * 65536 + (r - 256) * 256 + c];
        pw216[i] = __float2half_rn(v);
        return;
    }
    i -= 2097152;
    {
        int n = (int)(i >> 9), r = (int)(i & 511);
        pb2[i] = (r < 256) ? ab1[n * 256 + r] : cb1[n * 256 + r - 256];
    }
}

// ---------------- GRU gates (float4), writes fp32 hidden + fp16 mirror ----------------
__global__ void gru_gate4_k(const float* __restrict__ gx, const float* __restrict__ gh,
                            const float* __restrict__ h0, float* __restrict__ h,
                            __half* __restrict__ h16)
{
    int idx = blockIdx.x * blockDim.x + threadIdx.x;  // over BN_*64
    if (idx >= BN_ * 64) return;
    int m = idx >> 6;
    int c4 = (idx & 63) * 4;
    long long bx = (long long)m * 768 + c4;
    float4 xr = *(const float4*)(gx + bx);
    float4 xz = *(const float4*)(gx + bx + 256);
    float4 xn = *(const float4*)(gx + bx + 512);
    float4 hr = *(const float4*)(gh + bx);
    float4 hz = *(const float4*)(gh + bx + 256);
    float4 hn = *(const float4*)(gh + bx + 512);
    float4 h0v = *(const float4*)(h0 + (long long)m * 256 + c4);
    float4 o;
    {
        float r = 1.f / (1.f + expf(-(xr.x + hr.x)));
        float z = 1.f / (1.f + expf(-(xz.x + hz.x)));
        float nc = tanhf(xn.x + r * hn.x);
        o.x = (1.f - z) * nc + z * h0v.x;
    }
    {
        float r = 1.f / (1.f + expf(-(xr.y + hr.y)));
        float z = 1.f / (1.f + expf(-(xz.y + hz.y)));
        float nc = tanhf(xn.y + r * hn.y);
        o.y = (1.f - z) * nc + z * h0v.y;
    }
    {
        float r = 1.f / (1.f + expf(-(xr.z + hr.z)));
        float z = 1.f / (1.f + expf(-(xz.z + hz.z)));
        float nc = tanhf(xn.z + r * hn.z);
        o.z = (1.f - z) * nc + z * h0v.z;
    }
    {
        float r = 1.f / (1.f + expf(-(xr.w + hr.w)));
        float z = 1.f / (1.f + expf(-(xz.w + hz.w)));
        float nc = tanhf(xn.w + r * hn.w);
        o.w = (1.f - z) * nc + z * h0v.w;
    }
    *(float4*)(h + (long long)m * 256 + c4) = o;
    *(__half2*)(h16 + (long long)m * 256 + c4)     = __floats2half2_rn(o.x, o.y);
    *(__half2*)(h16 + (long long)m * 256 + c4 + 2) = __floats2half2_rn(o.z, o.w);
}

// ---------------- edge kernel v3: half2 node loads, register w2, register dec acc ----
__global__ __launch_bounds__(256) void edge_k(
    const __half* __restrict__ node,         // [B*N, 1024]: eHs|eHr|dHs|dHr
    const float* __restrict__ w2, const float* __restrict__ b2,
    float* __restrict__ rel, __half* __restrict__ Sout)
{
    int b = blockIdx.x;
    int tid = threadIdx.x;
    int w = tid >> 5, lane = tid & 31;

    // channels per lane: c = 2*lane + 64*q + {0,1}, q = 0..3
    float wx[4][KK], wy[4][KK];
    #pragma unroll
    for (int q = 0; q < 4; q++) {
        int c = 2 * lane + 64 * q;
        #pragma unroll
        for (int k = 0; k < KK; k++) {
            wx[q][k] = w2[k * SH + c];
            wy[q][k] = w2[k * SH + c + 1];
        }
    }

    const __half2* node2 = (const __half2*)node;
    long long base2 = (long long)b * Nn * 512;   // half2 units per batch
    for (int ii = 0; ii < 2; ii++) {
        int i = w * 2 + ii;
        float2 eR[4], dR[4], accD[4];
        #pragma unroll
        for (int q = 0; q < 4; q++) {
            int c2 = lane + 32 * q;
            eR[q] = __half22float2(node2[base2 + i * 512 + 128 + c2]);
            dR[q] = __half22float2(node2[base2 + i * 512 + 384 + c2]);
            accD[q].x = 0.f; accD[q].y = 0.f;
        }
        for (int j = 0; j < Nn; j++) {
            if (j == i) continue;
            float part[KK];
            #pragma unroll
            for (int k = 0; k < KK; k++) part[k] = 0.f;
            #pragma unroll
            for (int q = 0; q < 4; q++) {
                int c2 = lane + 32 * q;
                float2 ne = __half22float2(node2[base2 + j * 512 + c2]);
                float pe0 = fmaxf(ne.x + eR[q].x, 0.f);
                float pe1 = fmaxf(ne.y + eR[q].y, 0.f);
                #pragma unroll
                for (int k = 0; k < KK; k++)
                    part[k] += pe0 * wx[q][k] + pe1 * wy[q][k];
                float2 nd = __half22float2(node2[base2 + j * 512 + 256 + c2]);
                accD[q].x += fmaxf(nd.x + dR[q].x, 0.f);
                accD[q].y += fmaxf(nd.y + dR[q].y, 0.f);
            }
            #pragma unroll
            for (int k = 0; k < KK; k++) {
                #pragma unroll
                for (int off = 16; off; off >>= 1)
                    part[k] += __shfl_xor_sync(0xffffffffu, part[k], off);
                part[k] += b2[k];
            }
            if (lane == 0) {
                float mx = part[0];
                #pragma unroll
                for (int k = 1; k < KK; k++) mx = fmaxf(mx, part[k]);
                float e_[KK], s = 0.f;
                #pragma unroll
                for (int k = 0; k < KK; k++) { e_[k] = expf(part[k] - mx); s += e_[k]; }
                float inv = 1.f / s;
                int jj = (j < i) ? j : j - 1;
                long long eo = ((long long)b * Ee + i * 15 + jj) * KK;
                #pragma unroll
                for (int k = 0; k < KK; k++) rel[eo + k] = e_[k] * inv;
            }
        }
        __half2* So2 = (__half2*)Sout;
        long long sb2 = (long long)b * Nn * 128 + (long long)i * 128;
        #pragma unroll
        for (int q = 0; q < 4; q++)
            So2[sb2 + lane + 32 * q] = __floats2half2_rn(accD[q].x, accD[q].y);
    }
}

// ---------------- message aggregation + build ai16 = [obs, message] ----------------
__global__ __launch_bounds__(256) void message_k(
    const float* __restrict__ rel, const __half* __restrict__ msgs,
    const __half* __restrict__ obs16, __half* __restrict__ ai16)
{
    __shared__ float sRel[Ee * KK];  // 1920
    int b = blockIdx.x;
    int tid = threadIdx.x;
    for (int i = tid; i < Ee * KK; i += 256) sRel[i] = rel[(long long)b * Ee * KK + i];
    __syncthreads();

    int d = tid & 127;
    int g = tid >> 7;
    float acc[8];
    #pragma unroll
    for (int ii = 0; ii < 8; ii++) acc[ii] = 0.f;
    long long mb = (long long)b * Nn * KK * OBS;
    for (int j = 0; j < Nn; j++) {
        float mj[KK];
        #pragma unroll
        for (int k = 0; k < KK; k++) mj[k] = __half2float(msgs[mb + (j * KK + k) * OBS + d]);
        #pragma unroll
        for (int ii = 0; ii < 8; ii++) {
            int i = g * 8 + ii;
            if (i == j) continue;
            int jj = (j < i) ? j : j - 1;
            const float* r = &sRel[(i * 15 + jj) * KK];
            float a = acc[ii];
            #pragma unroll
            for (int k = 0; k < KK; k++) a += r[k] * mj[k];
            acc[ii] = a;
        }
    }
    long long ab = (long long)b * Nn * 2 * OBS;
    #pragma unroll
    for (int ii = 0; ii < 8; ii++) {
        int i = g * 8 + ii;
        ai16[ab + i * 2 * OBS + OBS + d] = __float2half_rn(acc[ii]);
    }
    for (int idx = tid; idx < Nn * OBS; idx += 256) {
        int i = idx >> 7, dd = idx & 127;
        ai16[ab + i * 2 * OBS + dd] = obs16[(long long)b * Nn * OBS + idx];
    }
}

// ---------------- fused tail: critic layer 2 + scm column 128 ----------------
__global__ void tail_k(const __half* __restrict__ h1, const float* __restrict__ w2,
                       const float* __restrict__ b2v, float* __restrict__ critic,
                       const __half* __restrict__ S16, const float* __restrict__ dec_w2,
                       const float* __restrict__ dec_b2, float* __restrict__ scm)
{
    int wg = (blockIdx.x * blockDim.x + threadIdx.x) >> 5;
    int lane = threadIdx.x & 31;
    if (wg < BN_) {
        int n = wg & 15;
        float s = 0.f;
        #pragma unroll
        for (int q = 0; q < 8; q++) {
            int c = lane + 32 * q;
            s += __half2float(h1[(long long)wg * 512 + 256 + c]) * w2[n * 256 + c];
        }
        #pragma unroll
        for (int off = 16; off; off >>= 1) s += __shfl_xor_sync(0xffffffffu, s, off);
        if (lane == 0) critic[wg] = s + b2v[n];
    } else if (wg < 2 * BN_) {
        int m = wg - BN_;
        float s = 0.f;
        #pragma unroll
        for (int q = 0; q < 8; q++) {
            int c = lane + 32 * q;
            s += __half2float(S16[(long long)m * 256 + c]) * dec_w2[128 * 256 + c];
        }
        #pragma unroll
        for (int off = 16; off; off >>= 1) s += __shfl_xor_sync(0xffffffffu, s, off);
        if (lane == 0)
            scm[(long long)m * 129 + 128] = (s + 15.0f * dec_b2[128]) * (1.f / 15.000001f);
    }
}

// ---------------- launch ----------------
extern "C" void kernel_launch(void* const* d_in, const int* in_sizes, int n_in,
                              void* d_out, int out_size)
{
    const float* obs    = (const float*)d_in[0];
    const float* rew    = (const float*)d_in[1];
    const float* h0     = (const float*)d_in[2];
    const float* w_ih   = (const float*)d_in[3];
    const float* w_hh   = (const float*)d_in[4];
    const float* b_ih   = (const float*)d_in[5];
    const float* b_hh   = (const float*)d_in[6];
    const float* enc_w1 = (const float*)d_in[7];
    const float* enc_b1 = (const float*)d_in[8];
    const float* enc_w2 = (const float*)d_in[9];
    const float* enc_b2 = (const float*)d_in[10];
    const float* dec_w1 = (const float*)d_in[11];
    const float* dec_b1 = (const float*)d_in[12];
    const float* dec_w2 = (const float*)d_in[13];
    const float* dec_b2 = (const float*)d_in[14];
    const float* msg_w  = (const float*)d_in[15];
    const float* msg_b  = (const float*)d_in[16];
    const float* aw1    = (const float*)d_in[17];
    const float* ab1    = (const float*)d_in[18];
    const float* aw2    = (const float*)d_in[19];
    const float* ab2    = (const float*)d_in[20];
    const float* cw1    = (const float*)d_in[21];
    const float* cb1    = (const float*)d_in[22];
    const float* cw2    = (const float*)d_in[23];
    const float* cb2    = (const float*)d_in[24];
    float* out = (float*)d_out;

    float *pgx, *pgh, *pb, *pb2, *pwihc;
    __half *obs16, *h016, *hid16, *node16, *S16, *msgs16, *ai16, *h116;
    __half *wih16, *whh16, *pw16, *dw216, *msgw16, *pw216, *aw216;
    cudaGetSymbolAddress((void**)&pgx,    g_gx);
    cudaGetSymbolAddress((void**)&pgh,    g_gh);
    cudaGetSymbolAddress((void**)&pb,     g_pb);
    cudaGetSymbolAddress((void**)&pb2,    g_pb2);
    cudaGetSymbolAddress((void**)&pwihc,  g_wihc);
    cudaGetSymbolAddress((void**)&obs16,  g_obs16);
    cudaGetSymbolAddress((void**)&h016,   g_h016);
    cudaGetSymbolAddress((void**)&hid16,  g_hid16);
    cudaGetSymbolAddress((void**)&node16, g_node16);
    cudaGetSymbolAddress((void**)&S16,    g_S16);
    cudaGetSymbolAddress((void**)&msgs16, g_msgs16);
    cudaGetSymbolAddress((void**)&ai16,   g_ai16);
    cudaGetSymbolAddress((void**)&h116,   g_h116);
    cudaGetSymbolAddress((void**)&wih16,  g_wih16);
    cudaGetSymbolAddress((void**)&whh16,  g_whh16);
    cudaGetSymbolAddress((void**)&pw16,   g_pw16);
    cudaGetSymbolAddress((void**)&dw216,  g_dw216);
    cudaGetSymbolAddress((void**)&msgw16, g_msgw16);
    cudaGetSymbolAddress((void**)&pw216,  g_pw216);
    cudaGetSymbolAddress((void**)&aw216,  g_aw216);

    float* actor  = out;                 // [B,N,32]    524288
    float* critic = out + 524288;        // [B,N,1]     16384
    float* scm    = out + 540672;        // [B,N,129]   2113536
    float* rel    = out + 2654208;       // [B,E,8]     1966080
    float* hid    = out + 4620288;       // [1,B*N,256] 4194304

    const float* NF = (const float*)0;
    float* NC = (float*)0;
    __half* NH = (__half*)0;

    // 1: fused prelude (weights + activations)
    prelude_k<<<(int)((PRE_TOT + 255) / 256), 256>>>(
        w_hh, dec_w2, msg_w, aw2, w_ih,
        enc_w1, enc_b1, dec_w1, dec_b1, aw1, ab1, cw1, cb1, obs, h0,
        whh16, dw216, msgw16, aw216, wih16, pwihc, pw16, pb, pw216, pb2,
        obs16, h016);

    // GRU: merged gx+gh in one launch (z=0: gx with rank-1 reward term; z=1: gh)
    {
        GD g0, g1;
        g0.A = obs16; g0.lda = 128; g0.B = wih16; g0.ldb = 128;
        g0.bias = b_ih; g0.rowv = rew; g0.colv = pwihc; g0.C = pgx; g0.K = 128;
        g1.A = h016; g1.lda = 256; g1.B = whh16; g1.ldb = 256;
        g1.bias = b_hh; g1.rowv = NF; g1.colv = NF; g1.C = pgh; g1.K = 256;
        gemm_pair<<<dim3(6, 128, 2), 256>>>(g0, g1, 768, 768);
    }
    gru_gate4_k<<<(BN_ * 64 + 255) / 256, 256>>>(pgx, pgh, h0, hid, hid16);

    // merged node projections + msgs (both [16384,1024] fp16 out)
    {
        GQ q0, q1;
        q0.A = hid16; q0.lda = 256; q0.B = pw16;   q0.ldb = 256;
        q0.bias = pb;    q0.Cq = node16; q0.K = 256;
        q1.A = obs16; q1.lda = 128; q1.B = msgw16; q1.ldb = 128;
        q1.bias = msg_b; q1.Cq = msgs16; q1.K = 128;
        gemm_pairq<<<dim3(8, 128, 2), 256>>>(q0, q1, 1024, 1024);
    }

    edge_k<<<Bz, 256>>>(node16, enc_w2, enc_b2, rel, S16);

    // scm_pred cols 0..127 = (S @ dec_w2^T + 15*b2) / 15.000001 (N=128; col 128 in tail_k)
    gemm_h5<<<dim3(1, 128, 1), 256>>>(
        S16, 256, 0, dw216, 256, 0, dec_b2, 0, 15.0f,
        scm, NH, 129, 0, BN_, 128, 256, 1.f / 15.000001f, 0);

    message_k<<<Bz, 256>>>(rel, msgs16, obs16, ai16);

    // fused actor+critic layer 1, batched over agent: [1024,512] per agent (fp16 out)
    gemm_h5<<<dim3(4, 8, 16), 256>>>(
        ai16, 4096, 256, pw216, 256, 512 * 256, pb2, 512, 1.f,
        NC, h116, 8192, 512, Bz, 512, 256, 1.f, 1);

    // actor layer 2 (N=32), batched over agent
    gemm_h5<<<dim3(1, 8, 16), 256>>>(
        h116, 8192, 512, aw216, 256, 32 * 256, ab2, 32, 1.f,
        actor, NH, 512, 32, Bz, 32, 256, 1.f, 0);

    // fused tail: critic layer 2 + scm col 128
    tail_k<<<(2 * BN_ * 32 + 255) / 256, 256>>>(
        h116, cw2, cb2, critic, S16, dec_w2, dec_b2, scm);
}

// round 17
// speedup vs baseline: 1.4577x; 1.0204x over previous
#include <cuda_runtime.h>
#include <cuda_fp16.h>
#include <math.h>
#include <string.h>

#define Bz   1024
#define Nn   16
#define OBS  128
#define ACTD 32
#define RH   256
#define SH   256
#define KK   8
#define Ee   240
#define BN_  (Bz*Nn)   // 16384

// ---------------- scratch (__device__ globals; no allocation) ----------------
__device__ float g_gx  [BN_*768];
__device__ float g_gh  [BN_*768];
__device__ float g_pb  [1024];
__device__ float g_pb2 [16*512];
__device__ float g_wihc[768];

__device__ __align__(256) __half g_obs16 [BN_*128];
__device__ __align__(256) __half g_h016  [BN_*256];
__device__ __align__(256) __half g_hid16 [BN_*256];
__device__ __align__(256) __half g_node16[BN_*1024];
__device__ __align__(256) __half g_S16   [BN_*256];
__device__ __align__(256) __half g_msgs16[BN_*1024];
__device__ __align__(256) __half g_ai16  [BN_*256];
__device__ __align__(256) __half g_h116  [BN_*512];
__device__ __align__(256) __half g_wih16 [768*128];
__device__ __align__(256) __half g_whh16 [768*256];
__device__ __align__(256) __half g_pw16  [1024*256];
__device__ __align__(256) __half g_dw216 [129*256];
__device__ __align__(256) __half g_msgw16[1024*128];
__device__ __align__(256) __half g_pw216 [16*512*256];
__device__ __align__(256) __half g_aw216 [16*32*256];

// ---------------- helpers ----------------
__device__ __forceinline__ unsigned smem_u32(const void* p) {
    unsigned a;
    asm("{ .reg .u64 t; cvta.to.shared.u64 t, %1; cvt.u32.u64 %0, t; }" : "=r"(a) : "l"(p));
    return a;
}

__device__ __forceinline__ void mma_fp16(float* c, const unsigned* a, const unsigned* b) {
    asm volatile(
        "mma.sync.aligned.m16n8k16.row.col.f32.f16.f16.f32 "
        "{%0,%1,%2,%3}, {%4,%5,%6,%7}, {%8,%9}, {%0,%1,%2,%3};"
        : "+f"(c[0]), "+f"(c[1]), "+f"(c[2]), "+f"(c[3])
        : "r"(a[0]), "r"(a[1]), "r"(a[2]), "r"(a[3]), "r"(b[0]), "r"(b[1]));
}

__device__ __forceinline__ void ldsm4(unsigned* r, unsigned addr) {
    asm volatile("ldmatrix.sync.aligned.m8n8.x4.shared.b16 {%0,%1,%2,%3}, [%4];"
                 : "=r"(r[0]), "=r"(r[1]), "=r"(r[2]), "=r"(r[3]) : "r"(addr));
}

#define CP16(dst, src, sz) \
    asm volatile("cp.async.ca.shared.global [%0], [%1], 16, %2;" \
                 :: "r"(dst), "l"(src), "r"(sz) : "memory")
#define CP_COMMIT() asm volatile("cp.async.commit_group;" ::: "memory")
#define CP_WAIT(n)  asm volatile("cp.async.wait_group %0;" :: "n"(n) : "memory")

// ---------------- GEMM body: 128x128 tile, BK=32, cp.async 4-stage ring ----------
#define ATB   10240                 // 128 rows * 80 bytes
#define STG_B (2 * ATB)             // one stage: A tile + B tile
#define GSMEM (4 * STG_B)           // 81920

__device__ __forceinline__ void gemm_body(
    const __half* __restrict__ A, int lda,
    const __half* __restrict__ B, int ldb,
    const float* __restrict__ bp, float biasMul,
    const float* __restrict__ rowv, const float* __restrict__ colv, int cvs,
    float* __restrict__ Cp, __half* __restrict__ Cq, int ldc,
    int row0, int col0, int N, int K, float scale, int relu)
{
    extern __shared__ __align__(16) char sm[];

    int t = threadIdx.x;
    int wid = t >> 5, lane = t & 31;
    int wm0 = (wid & 1) * 64;
    int wn0 = (wid >> 1) * 32;
    int mrow = lane >> 2, kr = lane & 3;

    float acc[16][4];
    #pragma unroll
    for (int i = 0; i < 16; i++)
        #pragma unroll
        for (int j = 0; j < 4; j++) acc[i][j] = 0.f;

    int srow = t >> 2, sg = t & 3;
    const __half* arow0 = A + (long long)(row0 + srow) * lda + sg * 8;
    const __half* arow1 = A + (long long)(row0 + srow + 64) * lda + sg * 8;
    int gc0 = col0 + srow, gc1 = col0 + srow + 64;
    const __half* brow0 = B + (long long)((gc0 < N) ? gc0 : 0) * ldb + sg * 8;
    const __half* brow1 = B + (long long)((gc1 < N) ? gc1 : 0) * ldb + sg * 8;
    unsigned szb0 = (gc0 < N) ? 16u : 0u;
    unsigned szb1 = (gc1 < N) ? 16u : 0u;

    unsigned sbase = smem_u32(sm);
    unsigned dA0 = sbase + srow * 80 + sg * 16;
    unsigned dA1 = dA0 + 64 * 80;
    unsigned dB0 = dA0 + ATB;
    unsigned dB1 = dA1 + ATB;

    int Cn = K >> 5;

    auto issue = [&](int c) {
        unsigned so = (unsigned)(c & 3) * STG_B;
        int kn = c << 5;
        CP16(dA0 + so, arow0 + kn, 16u);
        CP16(dA1 + so, arow1 + kn, 16u);
        CP16(dB0 + so, brow0 + kn, szb0);
        CP16(dB1 + so, brow1 + kn, szb1);
        CP_COMMIT();
    };

    issue(0); issue(1); issue(2);

    int tl = lane >> 3, rl = lane & 7;
    for (int c = 0; c < Cn; c++) {
        if (c + 2 < Cn)      { CP_WAIT(2); }
        else if (c + 1 < Cn) { CP_WAIT(1); }
        else                 { CP_WAIT(0); }
        __syncthreads();
        if (c + 3 < Cn) issue(c + 3);

        unsigned abase = sbase + (unsigned)(c & 3) * STG_B;
        unsigned bbase = abase + ATB;
        #pragma unroll
        for (int s = 0; s < 2; s++) {
            int ks = s * 16;
            unsigned afr[4][4], bfr[4][2];
            #pragma unroll
            for (int mt = 0; mt < 4; mt++) {
                int m0 = wm0 + mt * 16;
                int row = m0 + rl + ((tl & 1) << 3);
                int col = ks + ((tl >> 1) << 3);
                ldsm4(afr[mt], abase + row * 80 + col * 2);
            }
            #pragma unroll
            for (int nb = 0; nb < 2; nb++) {
                int n0 = wn0 + nb * 16;
                int row = n0 + rl + ((tl >> 1) << 3);
                int col = ks + ((tl & 1) << 3);
                unsigned r4[4];
                ldsm4(r4, bbase + row * 80 + col * 2);
                bfr[nb * 2 + 0][0] = r4[0]; bfr[nb * 2 + 0][1] = r4[1];
                bfr[nb * 2 + 1][0] = r4[2]; bfr[nb * 2 + 1][1] = r4[3];
            }
            #pragma unroll
            for (int mt = 0; mt < 4; mt++)
                #pragma unroll
                for (int nt = 0; nt < 4; nt++)
                    mma_fp16(acc[mt * 4 + nt], afr[mt], bfr[nt]);
        }
    }

    // ---- epilogue: uniform single-output paths, vectorized stores ----
    if (Cq) {
        #pragma unroll
        for (int mt = 0; mt < 4; mt++) {
            int r0 = row0 + wm0 + mt * 16 + mrow;
            #pragma unroll
            for (int nt = 0; nt < 4; nt++) {
                int gc = col0 + wn0 + nt * 8 + 2 * kr;
                const float* cc = acc[mt * 4 + nt];
                #pragma unroll
                for (int h = 0; h < 2; h++) {
                    int gr = r0 + h * 8;
                    float v0 = cc[h * 2 + 0], v1 = cc[h * 2 + 1];
                    if (bp) { v0 += bp[gc] * biasMul; v1 += bp[gc + 1] * biasMul; }
                    if (rowv) {
                        float rv = rowv[gr];
                        v0 += rv * colv[(long long)gc * cvs];
                        v1 += rv * colv[(long long)(gc + 1) * cvs];
                    }
                    v0 *= scale; v1 *= scale;
                    if (relu) { v0 = fmaxf(v0, 0.f); v1 = fmaxf(v1, 0.f); }
                    if (gc + 1 < N)
                        *(__half2*)(Cq + (long long)gr * ldc + gc) = __floats2half2_rn(v0, v1);
                    else if (gc < N)
                        Cq[(long long)gr * ldc + gc] = __float2half_rn(v0);
                }
            }
        }
    } else {
        bool al = (ldc & 1) == 0;
        #pragma unroll
        for (int mt = 0; mt < 4; mt++) {
            int r0 = row0 + wm0 + mt * 16 + mrow;
            #pragma unroll
            for (int nt = 0; nt < 4; nt++) {
                int gc = col0 + wn0 + nt * 8 + 2 * kr;
                const float* cc = acc[mt * 4 + nt];
                #pragma unroll
                for (int h = 0; h < 2; h++) {
                    int gr = r0 + h * 8;
                    float v0 = cc[h * 2 + 0], v1 = cc[h * 2 + 1];
                    if (bp) { v0 += bp[gc] * biasMul; v1 += bp[gc + 1] * biasMul; }
                    if (rowv) {
                        float rv = rowv[gr];
                        v0 += rv * colv[(long long)gc * cvs];
                        v1 += rv * colv[(long long)(gc + 1) * cvs];
                    }
                    v0 *= scale; v1 *= scale;
                    if (relu) { v0 = fmaxf(v0, 0.f); v1 = fmaxf(v1, 0.f); }
                    long long base = (long long)gr * ldc + gc;
                    if (al && gc + 1 < N) {
                        float2 o; o.x = v0; o.y = v1;
                        *(float2*)(Cp + base) = o;
                    } else {
                        if (gc < N) Cp[base] = v0;
                        if (gc + 1 < N) Cp[base + 1] = v1;
                    }
                }
            }
        }
    }
}

// ---------------- generic single-GEMM wrapper (z-batched) ----------------
__global__ void __launch_bounds__(256, 2) gemm_h5(
    const __half* __restrict__ A, int lda, long long sA,
    const __half* __restrict__ B, int ldb, long long sB,
    const float* __restrict__ bias, long long sBias, float biasMul,
    float* __restrict__ C, __half* __restrict__ C16, int ldc, long long sC,
    int M, int N, int K, float scale, int relu)
{
    int bz = blockIdx.z;
    const float* bp = bias ? bias + (long long)bz * sBias : (const float*)0;
    gemm_body(A + (long long)bz * sA, lda, B + (long long)bz * sB, ldb,
              bp, biasMul, (const float*)0, (const float*)0, 0,
              C ? C + (long long)bz * sC : (float*)0,
              C16 ? C16 + (long long)bz * sC : (__half*)0, ldc,
              blockIdx.y * 128, blockIdx.x * 128, N, K, scale, relu);
}

// ---------------- paired GEMM descriptors ----------------
struct GD {
    const __half* A; int lda;
    const __half* B; int ldb;
    const float* bias;
    const float* rowv; const float* colv;
    float* C;
    int K;
};

__global__ void __launch_bounds__(256, 2) gemm_pair(GD g0, GD g1, int N, int ldc)
{
    const GD& g = (blockIdx.z == 0) ? g0 : g1;
    gemm_body(g.A, g.lda, g.B, g.ldb, g.bias, 1.f, g.rowv, g.colv, 1,
              g.C, (__half*)0, ldc,
              blockIdx.y * 128, blockIdx.x * 128, N, g.K, 1.f, 0);
}

// fp16-out pair (node projections + msgs)
struct GQ {
    const __half* A; int lda;
    const __half* B; int ldb;
    const float* bias;
    __half* Cq;
    int K;
};

__global__ void __launch_bounds__(256, 2) gemm_pairq(GQ g0, GQ g1, int N, int ldc)
{
    const GQ& g = (blockIdx.z == 0) ? g0 : g1;
    gemm_body(g.A, g.lda, g.B, g.ldb, g.bias, 1.f,
              (const float*)0, (const float*)0, 0,
              (float*)0, g.Cq, ldc,
              blockIdx.y * 128, blockIdx.x * 128, N, g.K, 1.f, 0);
}

// ---------------- fused prelude (weights + activations in one launch) --------
#define PRE_W_TOT (196608 + 33024 + 131072 + 131072 + 98304 + 768 + 262144 + 1024 + 2097152 + 8192)
#define PRE_A_TOT ((BN_ * 128 + BN_ * 256) / 4)
#define PRE_TOT   (PRE_W_TOT + PRE_A_TOT)

__global__ void prelude_k(
    const float* __restrict__ w_hh, const float* __restrict__ dec_w2,
    const float* __restrict__ msg_w, const float* __restrict__ aw2,
    const float* __restrict__ w_ih,
    const float* __restrict__ ew1, const float* __restrict__ eb1,
    const float* __restrict__ dw1, const float* __restrict__ db1,
    const float* __restrict__ aw1, const float* __restrict__ ab1,
    const float* __restrict__ cw1, const float* __restrict__ cb1,
    const float* __restrict__ obs, const float* __restrict__ h0,
    __half* __restrict__ whh16, __half* __restrict__ dw216,
    __half* __restrict__ msgw16, __half* __restrict__ aw216,
    __half* __restrict__ wih16, float* __restrict__ wihc,
    __half* __restrict__ pw16, float* __restrict__ pb,
    __half* __restrict__ pw216, float* __restrict__ pb2,
    __half* __restrict__ obs16, __half* __restrict__ h016)
{
    long long i = (long long)blockIdx.x * 256 + threadIdx.x;
    if (i >= PRE_TOT) return;
    if (i >= PRE_W_TOT) {
        long long i4 = i - PRE_W_TOT;
        const float* s;
        __half* d;
        long long off;
        if (i4 < BN_ * 128 / 4) { s = obs; d = obs16; off = i4 * 4; }
        else { s = h0; d = h016; off = (i4 - BN_ * 128 / 4) * 4; }
        float4 v = *(const float4*)(s + off);
        *(__half2*)(d + off)     = __floats2half2_rn(v.x, v.y);
        *(__half2*)(d + off + 2) = __floats2half2_rn(v.z, v.w);
        return;
    }
    if (i < 196608) { whh16[i] = __float2half_rn(w_hh[i]); return; }
    i -= 196608;
    if (i < 33024) { dw216[i] = __float2half_rn(dec_w2[i]); return; }
    i -= 33024;
    if (i < 131072) { msgw16[i] = __float2half_rn(msg_w[i]); return; }
    i -= 131072;
    if (i < 131072) { aw216[i] = __float2half_rn(aw2[i]); return; }
    i -= 131072;
    if (i < 98304) {
        int r = (int)(i >> 7), c = (int)(i & 127);
        wih16[i] = __float2half_rn(w_ih[r * 129 + c]);
        return;
    }
    i -= 98304;
    if (i < 768) { wihc[i] = w_ih[i * 129 + 128]; return; }
    i -= 768;
    if (i < 262144) {
        int r = (int)(i >> 8), c = (int)(i & 255);
        float v;
        if (r < 256)      v = ew1[r * 512 + c];
        else if (r < 512) v = ew1[(r - 256) * 512 + 256 + c];
        else if (r < 768) v = dw1[(r - 512) * 512 + c];
        else              v = dw1[(r - 768) * 512 + 256 + c];
        pw16[i] = __float2half_rn(v);
        return;
    }
    i -= 262144;
    if (i < 1024) {
        int r = (int)i;
        float v = 0.f;
        if (r >= 256 && r < 512) v = eb1[r - 256];
        else if (r >= 768)       v = db1[r - 768];
        pb[r] = v;
        return;
    }
    i -= 1024;
    if (i < 2097152) {
        int n = (int)(i >> 17);
        int r = (int)((i >> 8) & 511);
        int c = (int)(i & 255);
        float v = (r < 256) ? aw1[n * 65536 + r * 256 + c]
                            : cw1[n * 65536 + (r - 256) * 256 + c];
        pw216[i] = __float2half_rn(v);
        return;
    }
    i -= 2097152;
    {
        int n = (int)(i >> 9), r = (int)(i & 511);
        pb2[i] = (r < 256) ? ab1[n * 256 + r] : cb1[n * 256 + r - 256];
    }
}

// ---------------- GRU gates (float4), writes fp32 hidden + fp16 mirror ----------------
__global__ void gru_gate4_k(const float* __restrict__ gx, const float* __restrict__ gh,
                            const float* __restrict__ h0, float* __restrict__ h,
                            __half* __restrict__ h16)
{
    int idx = blockIdx.x * blockDim.x + threadIdx.x;  // over BN_*64
    if (idx >= BN_ * 64) return;
    int m = idx >> 6;
    int c4 = (idx & 63) * 4;
    long long bx = (long long)m * 768 + c4;
    float4 xr = *(const float4*)(gx + bx);
    float4 xz = *(const float4*)(gx + bx + 256);
    float4 xn = *(const float4*)(gx + bx + 512);
    float4 hr = *(const float4*)(gh + bx);
    float4 hz = *(const float4*)(gh + bx + 256);
    float4 hn = *(const float4*)(gh + bx + 512);
    float4 h0v = *(const float4*)(h0 + (long long)m * 256 + c4);
    float4 o;
    {
        float r = 1.f / (1.f + expf(-(xr.x + hr.x)));
        float z = 1.f / (1.f + expf(-(xz.x + hz.x)));
        float nc = tanhf(xn.x + r * hn.x);
        o.x = (1.f - z) * nc + z * h0v.x;
    }
    {
        float r = 1.f / (1.f + expf(-(xr.y + hr.y)));
        float z = 1.f / (1.f + expf(-(xz.y + hz.y)));
        float nc = tanhf(xn.y + r * hn.y);
        o.y = (1.f - z) * nc + z * h0v.y;
    }
    {
        float r = 1.f / (1.f + expf(-(xr.z + hr.z)));
        float z = 1.f / (1.f + expf(-(xz.z + hz.z)));
        float nc = tanhf(xn.z + r * hn.z);
        o.z = (1.f - z) * nc + z * h0v.z;
    }
    {
        float r = 1.f / (1.f + expf(-(xr.w + hr.w)));
        float z = 1.f / (1.f + expf(-(xz.w + hz.w)));
        float nc = tanhf(xn.w + r * hn.w);
        o.w = (1.f - z) * nc + z * h0v.w;
    }
    *(float4*)(h + (long long)m * 256 + c4) = o;
    *(__half2*)(h16 + (long long)m * 256 + c4)     = __floats2half2_rn(o.x, o.y);
    *(__half2*)(h16 + (long long)m * 256 + c4 + 2) = __floats2half2_rn(o.z, o.w);
}

// ---------------- edge kernel v3: half2 node loads, register w2, register dec acc ----
__global__ __launch_bounds__(256) void edge_k(
    const __half* __restrict__ node,         // [B*N, 1024]: eHs|eHr|dHs|dHr
    const float* __restrict__ w2, const float* __restrict__ b2,
    float* __restrict__ rel, __half* __restrict__ Sout)
{
    int b = blockIdx.x;
    int tid = threadIdx.x;
    int w = tid >> 5, lane = tid & 31;

    float wx[4][KK], wy[4][KK];
    #pragma unroll
    for (int q = 0; q < 4; q++) {
        int c = 2 * lane + 64 * q;
        #pragma unroll
        for (int k = 0; k < KK; k++) {
            wx[q][k] = w2[k * SH + c];
            wy[q][k] = w2[k * SH + c + 1];
        }
    }

    const __half2* node2 = (const __half2*)node;
    long long base2 = (long long)b * Nn * 512;
    for (int ii = 0; ii < 2; ii++) {
        int i = w * 2 + ii;
        float2 eR[4], dR[4], accD[4];
        #pragma unroll
        for (int q = 0; q < 4; q++) {
            int c2 = lane + 32 * q;
            eR[q] = __half22float2(node2[base2 + i * 512 + 128 + c2]);
            dR[q] = __half22float2(node2[base2 + i * 512 + 384 + c2]);
            accD[q].x = 0.f; accD[q].y = 0.f;
        }
        for (int j = 0; j < Nn; j++) {
            if (j == i) continue;
            float part[KK];
            #pragma unroll
            for (int k = 0; k < KK; k++) part[k] = 0.f;
            #pragma unroll
            for (int q = 0; q < 4; q++) {
                int c2 = lane + 32 * q;
                float2 ne = __half22float2(node2[base2 + j * 512 + c2]);
                float pe0 = fmaxf(ne.x + eR[q].x, 0.f);
                float pe1 = fmaxf(ne.y + eR[q].y, 0.f);
                #pragma unroll
                for (int k = 0; k < KK; k++)
                    part[k] += pe0 * wx[q][k] + pe1 * wy[q][k];
                float2 nd = __half22float2(node2[base2 + j * 512 + 256 + c2]);
                accD[q].x += fmaxf(nd.x + dR[q].x, 0.f);
                accD[q].y += fmaxf(nd.y + dR[q].y, 0.f);
            }
            #pragma unroll
            for (int k = 0; k < KK; k++) {
                #pragma unroll
                for (int off = 16; off; off >>= 1)
                    part[k] += __shfl_xor_sync(0xffffffffu, part[k], off);
                part[k] += b2[k];
            }
            if (lane == 0) {
                float mx = part[0];
                #pragma unroll
                for (int k = 1; k < KK; k++) mx = fmaxf(mx, part[k]);
                float e_[KK], s = 0.f;
                #pragma unroll
                for (int k = 0; k < KK; k++) { e_[k] = expf(part[k] - mx); s += e_[k]; }
                float inv = 1.f / s;
                int jj = (j < i) ? j : j - 1;
                long long eo = ((long long)b * Ee + i * 15 + jj) * KK;
                #pragma unroll
                for (int k = 0; k < KK; k++) rel[eo + k] = e_[k] * inv;
            }
        }
        __half2* So2 = (__half2*)Sout;
        long long sb2 = (long long)b * Nn * 128 + (long long)i * 128;
        #pragma unroll
        for (int q = 0; q < 4; q++)
            So2[sb2 + lane + 32 * q] = __floats2half2_rn(accD[q].x, accD[q].y);
    }
}

// ---------------- message aggregation + build ai16 = [obs, message] ----------------
__global__ __launch_bounds__(256) void message_k(
    const float* __restrict__ rel, const __half* __restrict__ msgs,
    const __half* __restrict__ obs16, __half* __restrict__ ai16)
{
    __shared__ float sRel[Ee * KK];  // 1920
    int b = blockIdx.x;
    int tid = threadIdx.x;
    for (int i = tid; i < Ee * KK; i += 256) sRel[i] = rel[(long long)b * Ee * KK + i];
    __syncthreads();

    int d = tid & 127;
    int g = tid >> 7;
    float acc[8];
    #pragma unroll
    for (int ii = 0; ii < 8; ii++) acc[ii] = 0.f;
    long long mb = (long long)b * Nn * KK * OBS;
    for (int j = 0; j < Nn; j++) {
        float mj[KK];
        #pragma unroll
        for (int k = 0; k < KK; k++) mj[k] = __half2float(msgs[mb + (j * KK + k) * OBS + d]);
        #pragma unroll
        for (int ii = 0; ii < 8; ii++) {
            int i = g * 8 + ii;
            if (i == j) continue;
            int jj = (j < i) ? j : j - 1;
            const float* r = &sRel[(i * 15 + jj) * KK];
            float a = acc[ii];
            #pragma unroll
            for (int k = 0; k < KK; k++) a += r[k] * mj[k];
            acc[ii] = a;
        }
    }
    long long ab = (long long)b * Nn * 2 * OBS;
    #pragma unroll
    for (int ii = 0; ii < 8; ii++) {
        int i = g * 8 + ii;
        ai16[ab + i * 2 * OBS + OBS + d] = __float2half_rn(acc[ii]);
    }
    for (int idx = tid; idx < Nn * OBS; idx += 256) {
        int i = idx >> 7, dd = idx & 127;
        ai16[ab + i * 2 * OBS + dd] = obs16[(long long)b * Nn * OBS + idx];
    }
}

// ---------------- fused tail: critic layer 2 + scm column 128 ----------------
__global__ void tail_k(const __half* __restrict__ h1, const float* __restrict__ w2,
                       const float* __restrict__ b2v, float* __restrict__ critic,
                       const __half* __restrict__ S16, const float* __restrict__ dec_w2,
                       const float* __restrict__ dec_b2, float* __restrict__ scm)
{
    int wg = (blockIdx.x * blockDim.x + threadIdx.x) >> 5;
    int lane = threadIdx.x & 31;
    if (wg < BN_) {
        int n = wg & 15;
        float s = 0.f;
        #pragma unroll
        for (int q = 0; q < 8; q++) {
            int c = lane + 32 * q;
            s += __half2float(h1[(long long)wg * 512 + 256 + c]) * w2[n * 256 + c];
        }
        #pragma unroll
        for (int off = 16; off; off >>= 1) s += __shfl_xor_sync(0xffffffffu, s, off);
        if (lane == 0) critic[wg] = s + b2v[n];
    } else if (wg < 2 * BN_) {
        int m = wg - BN_;
        float s = 0.f;
        #pragma unroll
        for (int q = 0; q < 8; q++) {
            int c = lane + 32 * q;
            s += __half2float(S16[(long long)m * 256 + c]) * dec_w2[128 * 256 + c];
        }
        #pragma unroll
        for (int off = 16; off; off >>= 1) s += __shfl_xor_sync(0xffffffffu, s, off);
        if (lane == 0)
            scm[(long long)m * 129 + 128] = (s + 15.0f * dec_b2[128]) * (1.f / 15.000001f);
    }
}

// ---------------- launch ----------------
extern "C" void kernel_launch(void* const* d_in, const int* in_sizes, int n_in,
                              void* d_out, int out_size)
{
    const float* obs    = (const float*)d_in[0];
    const float* rew    = (const float*)d_in[1];
    const float* h0     = (const float*)d_in[2];
    const float* w_ih   = (const float*)d_in[3];
    const float* w_hh   = (const float*)d_in[4];
    const float* b_ih   = (const float*)d_in[5];
    const float* b_hh   = (const float*)d_in[6];
    const float* enc_w1 = (const float*)d_in[7];
    const float* enc_b1 = (const float*)d_in[8];
    const float* enc_w2 = (const float*)d_in[9];
    const float* enc_b2 = (const float*)d_in[10];
    const float* dec_w1 = (const float*)d_in[11];
    const float* dec_b1 = (const float*)d_in[12];
    const float* dec_w2 = (const float*)d_in[13];
    const float* dec_b2 = (const float*)d_in[14];
    const float* msg_w  = (const float*)d_in[15];
    const float* msg_b  = (const float*)d_in[16];
    const float* aw1    = (const float*)d_in[17];
    const float* ab1    = (const float*)d_in[18];
    const float* aw2    = (const float*)d_in[19];
    const float* ab2    = (const float*)d_in[20];
    const float* cw1    = (const float*)d_in[21];
    const float* cb1    = (const float*)d_in[22];
    const float* cw2    = (const float*)d_in[23];
    const float* cb2    = (const float*)d_in[24];
    float* out = (float*)d_out;

    float *pgx, *pgh, *pb, *pb2, *pwihc;
    __half *obs16, *h016, *hid16, *node16, *S16, *msgs16, *ai16, *h116;
    __half *wih16, *whh16, *pw16, *dw216, *msgw16, *pw216, *aw216;
    cudaGetSymbolAddress((void**)&pgx,    g_gx);
    cudaGetSymbolAddress((void**)&pgh,    g_gh);
    cudaGetSymbolAddress((void**)&pb,     g_pb);
    cudaGetSymbolAddress((void**)&pb2,    g_pb2);
    cudaGetSymbolAddress((void**)&pwihc,  g_wihc);
    cudaGetSymbolAddress((void**)&obs16,  g_obs16);
    cudaGetSymbolAddress((void**)&h016,   g_h016);
    cudaGetSymbolAddress((void**)&hid16,  g_hid16);
    cudaGetSymbolAddress((void**)&node16, g_node16);
    cudaGetSymbolAddress((void**)&S16,    g_S16);
    cudaGetSymbolAddress((void**)&msgs16, g_msgs16);
    cudaGetSymbolAddress((void**)&ai16,   g_ai16);
    cudaGetSymbolAddress((void**)&h116,   g_h116);
    cudaGetSymbolAddress((void**)&wih16,  g_wih16);
    cudaGetSymbolAddress((void**)&whh16,  g_whh16);
    cudaGetSymbolAddress((void**)&pw16,   g_pw16);
    cudaGetSymbolAddress((void**)&dw216,  g_dw216);
    cudaGetSymbolAddress((void**)&msgw16, g_msgw16);
    cudaGetSymbolAddress((void**)&pw216,  g_pw216);
    cudaGetSymbolAddress((void**)&aw216,  g_aw216);

    float* actor  = out;                 // [B,N,32]    524288
    float* critic = out + 524288;        // [B,N,1]     16384
    float* scm    = out + 540672;        // [B,N,129]   2113536
    float* rel    = out + 2654208;       // [B,E,8]     1966080
    float* hid    = out + 4620288;       // [1,B*N,256] 4194304

    const float* NF = (const float*)0;
    float* NC = (float*)0;
    __half* NH = (__half*)0;

    cudaFuncSetAttribute(gemm_h5,    cudaFuncAttributeMaxDynamicSharedMemorySize, GSMEM);
    cudaFuncSetAttribute(gemm_pair,  cudaFuncAttributeMaxDynamicSharedMemorySize, GSMEM);
    cudaFuncSetAttribute(gemm_pairq, cudaFuncAttributeMaxDynamicSharedMemorySize, GSMEM);

    // 1: fused prelude (weights + activations)
    prelude_k<<<(int)((PRE_TOT + 255) / 256), 256>>>(
        w_hh, dec_w2, msg_w, aw2, w_ih,
        enc_w1, enc_b1, dec_w1, dec_b1, aw1, ab1, cw1, cb1, obs, h0,
        whh16, dw216, msgw16, aw216, wih16, pwihc, pw16, pb, pw216, pb2,
        obs16, h016);

    // GRU: merged gx+gh in one launch (z=0: gx with rank-1 reward term; z=1: gh)
    {
        GD g0, g1;
        g0.A = obs16; g0.lda = 128; g0.B = wih16; g0.ldb = 128;
        g0.bias = b_ih; g0.rowv = rew; g0.colv = pwihc; g0.C = pgx; g0.K = 128;
        g1.A = h016; g1.lda = 256; g1.B = whh16; g1.ldb = 256;
        g1.bias = b_hh; g1.rowv = NF; g1.colv = NF; g1.C = pgh; g1.K = 256;
        gemm_pair<<<dim3(6, 128, 2), 256, GSMEM>>>(g0, g1, 768, 768);
    }
    gru_gate4_k<<<(BN_ * 64 + 255) / 256, 256>>>(pgx, pgh, h0, hid, hid16);

    // merged node projections + msgs (both [16384,1024] fp16 out)
    {
        GQ q0, q1;
        q0.A = hid16; q0.lda = 256; q0.B = pw16;   q0.ldb = 256;
        q0.bias = pb;    q0.Cq = node16; q0.K = 256;
        q1.A = obs16; q1.lda = 128; q1.B = msgw16; q1.ldb = 128;
        q1.bias = msg_b; q1.Cq = msgs16; q1.K = 128;
        gemm_pairq<<<dim3(8, 128, 2), 256, GSMEM>>>(q0, q1, 1024, 1024);
    }

    edge_k<<<Bz, 256>>>(node16, enc_w2, enc_b2, rel, S16);

    // scm_pred cols 0..127 (col 128 in tail_k)
    gemm_h5<<<dim3(1, 128, 1), 256, GSMEM>>>(
        S16, 256, 0, dw216, 256, 0, dec_b2, 0, 15.0f,
        scm, NH, 129, 0, BN_, 128, 256, 1.f / 15.000001f, 0);

    message_k<<<Bz, 256>>>(rel, msgs16, obs16, ai16);

    // fused actor+critic layer 1, batched over agent: [1024,512] per agent (fp16 out)
    gemm_h5<<<dim3(4, 8, 16), 256, GSMEM>>>(
        ai16, 4096, 256, pw216, 256, 512 * 256, pb2, 512, 1.f,
        NC, h116, 8192, 512, Bz, 512, 256, 1.f, 1);

    // actor layer 2 (N=32), batched over agent
    gemm_h5<<<dim3(1, 8, 16), 256, GSMEM>>>(
        h116, 8192, 512, aw216, 256, 32 * 256, ab2, 32, 1.f,
        actor, NH, 512, 32, Bz, 32, 256, 1.f, 0);

    // fused tail: critic layer 2 + scm col 128
    tail_k<<<(2 * BN_ * 32 + 255) / 256, 256>>>(
        h116, cw2, cb2, critic, S16, dec_w2, dec_b2, scm);
}